// round 2
// baseline (speedup 1.0000x reference)
#include <cuda_runtime.h>
#include <cuda_bf16.h>
#include <math.h>

// ---------------------------------------------------------------------------
// GWNet2: B=64, N=1024, L=13, RC=DC=32, SC=256, EC=512, OUT=12, LAYERS=8
// Internal layout for h/m/x: [B][L][C][N] (N innermost, contiguous rows of 1024)
// skip / e1 layout: [C][B*N]
// ---------------------------------------------------------------------------

#define NB 64
#define NN 1024
#define NC 32
#define NSC 256
#define NEC 512
#define NOUT 12

// device scratch (allocation-free rule: __device__ globals)
__device__ float g_hA[64 * 13 * 32 * 1024];   // 27,262,976
__device__ float g_hB[64 * 12 * 32 * 1024];   // 25,165,824
__device__ float g_m [64 * 12 * 32 * 1024];   // 25,165,824
__device__ float g_x12[64 * 12 * 32 * 2048];  // 50,331,648  (x1 | x2 per row)
__device__ float g_Bm[1024 * 2048];           // [ADP | ADP^2], row-major, ld=2048
__device__ float g_skip[256 * 64 * 1024];     // [C=256][B*N]
__device__ float g_e1 [512 * 64 * 1024];      // [C=512][B*N]

// ---------------------------------------------------------------------------
// adp = softmax(relu(nv1 @ nv2), axis=1); one block per row v
// ---------------------------------------------------------------------------
__global__ __launch_bounds__(256) void k_adp(const float* __restrict__ nv1,
                                             const float* __restrict__ nv2,
                                             float* __restrict__ Bm) {
    __shared__ float red[256];
    int v = blockIdx.x, tid = threadIdx.x;
    float n1[10];
#pragma unroll
    for (int k = 0; k < 10; k++) n1[k] = nv1[v * 10 + k];
    float a[4];
#pragma unroll
    for (int j = 0; j < 4; j++) {
        int w = tid + j * 256;
        float s = 0.f;
#pragma unroll
        for (int k = 0; k < 10; k++) s += n1[k] * nv2[k * 1024 + w];
        a[j] = fmaxf(s, 0.f);
    }
    float mx = fmaxf(fmaxf(a[0], a[1]), fmaxf(a[2], a[3]));
    red[tid] = mx; __syncthreads();
    for (int s = 128; s > 0; s >>= 1) {
        if (tid < s) red[tid] = fmaxf(red[tid], red[tid + s]);
        __syncthreads();
    }
    mx = red[0]; __syncthreads();
    float e[4]; float sum = 0.f;
#pragma unroll
    for (int j = 0; j < 4; j++) { e[j] = expf(a[j] - mx); sum += e[j]; }
    red[tid] = sum; __syncthreads();
    for (int s = 128; s > 0; s >>= 1) {
        if (tid < s) red[tid] += red[tid + s];
        __syncthreads();
    }
    float inv = 1.f / red[0];
#pragma unroll
    for (int j = 0; j < 4; j++) Bm[(long)v * 2048 + tid + j * 256] = e[j] * inv;
}

// ---------------------------------------------------------------------------
// start conv: h[b][l][c][n] = sw[c][0]*x[b,0,n,l] + sw[c][1]*x[b,1,n,l] + sb[c]
// grid: (64*13, 4), 256 thr
// ---------------------------------------------------------------------------
__global__ __launch_bounds__(256) void k_start(const float* __restrict__ x,
                                               const float* __restrict__ sw,
                                               const float* __restrict__ sb,
                                               float* __restrict__ h) {
    int bl = blockIdx.x;
    int b = bl / 13, l = bl - b * 13;
    int n = blockIdx.y * 256 + threadIdx.x;
    float x0 = x[(((long)b * 2 + 0) * 1024 + n) * 13 + l];
    float x1 = x[(((long)b * 2 + 1) * 1024 + n) * 13 + l];
    float* hb = h + ((long)(b * 13 + l) * 32) * 1024 + n;
#pragma unroll
    for (int c = 0; c < 32; c++)
        hb[(long)c * 1024] = sw[c * 2] * x0 + sw[c * 2 + 1] * x1 + sb[c];
}

// ---------------------------------------------------------------------------
// dilated conv + tanh*sigmoid gate
// m[b][l][co][n] = tanh(fw0@h[l] + fw1@h[l+d] + fb) * sig(gw0@h[l] + gw1@h[l+d] + gb)
// grid: (64*L1, 16), 256 thr; block handles (b,l, 64 n's), 4 co-groups of 8
// ---------------------------------------------------------------------------
__global__ __launch_bounds__(256) void k_dconv(const float* __restrict__ h,
                                               const float* __restrict__ fw,
                                               const float* __restrict__ fb,
                                               const float* __restrict__ gw,
                                               const float* __restrict__ gb,
                                               float* __restrict__ m,
                                               int L0, int L1, int d) {
    __shared__ float s_in[2][32][64];
    __shared__ float4 s_w[32][32];
    __shared__ float s_fb[32], s_gb[32];
    int bl = blockIdx.x;
    int b = bl / L1, l = bl - b * L1;
    int n0 = blockIdx.y * 64;
    int tid = threadIdx.x;
    for (int idx = tid; idx < 1024; idx += 256) {
        int co = idx >> 5, ci = idx & 31;
        int o = (co * 32 + ci) * 2;
        s_w[co][ci] = make_float4(fw[o], fw[o + 1], gw[o], gw[o + 1]);
    }
    if (tid < 32) { s_fb[tid] = fb[tid]; s_gb[tid] = gb[tid]; }
    const float* hb = h + ((long)(b * L0 + l) * 32) * 1024 + n0;
    for (int idx = tid; idx < 4096; idx += 256) {
        int tap = idx >> 11, ci = (idx >> 6) & 31, nl = idx & 63;
        s_in[tap][ci][nl] = hb[((long)(tap * d) * 32 + ci) * 1024 + nl];
    }
    __syncthreads();
    int nl = tid & 63, cg = tid >> 6;
    float* mo = m + ((long)(b * L1 + l) * 32) * 1024 + n0 + nl;
#pragma unroll
    for (int u = 0; u < 8; u++) {
        int co = cg * 8 + u;
        float fa = s_fb[co], ga = s_gb[co];
#pragma unroll
        for (int ci = 0; ci < 32; ci++) {
            float v0 = s_in[0][ci][nl], v1 = s_in[1][ci][nl];
            float4 w = s_w[co][ci];
            fa += w.x * v0 + w.y * v1;
            ga += w.z * v0 + w.w * v1;
        }
        mo[(long)co * 1024] = tanhf(fa) * (1.f / (1.f + expf(-ga)));
    }
}

// ---------------------------------------------------------------------------
// skip accumulation (last timestep only):
// skip[co][b*1024+n] (+)= sum_ci sw[co][ci]*m[b][L1-1][ci][n] + sb[co]
// grid: (64, 8), 256 thr (thread == co)
// ---------------------------------------------------------------------------
__global__ __launch_bounds__(256) void k_skip(const float* __restrict__ m,
                                              const float* __restrict__ sw,
                                              const float* __restrict__ sb,
                                              float* __restrict__ skip,
                                              int L1, int first) {
    __shared__ float s_m[32][128];
    int b = blockIdx.x;
    int n0 = blockIdx.y * 128;
    int tid = threadIdx.x;
    const float* mb = m + ((long)(b * L1 + (L1 - 1)) * 32) * 1024 + n0;
    for (int idx = tid; idx < 4096; idx += 256) {
        int ci = idx >> 7, nl = idx & 127;
        s_m[ci][nl] = mb[(long)ci * 1024 + nl];
    }
    __syncthreads();
    float w[32];
#pragma unroll
    for (int ci = 0; ci < 32; ci++) w[ci] = sw[tid * 32 + ci];
    float bias = sb[tid];
    float* so = skip + (long)tid * 65536 + b * 1024 + n0;
    for (int n = 0; n < 128; n += 4) {
        float a0 = bias, a1 = bias, a2 = bias, a3 = bias;
#pragma unroll
        for (int ci = 0; ci < 32; ci++) {
            float4 v = *(const float4*)&s_m[ci][n];
            a0 += w[ci] * v.x; a1 += w[ci] * v.y;
            a2 += w[ci] * v.z; a3 += w[ci] * v.w;
        }
        if (first) {
            so[n] = a0; so[n + 1] = a1; so[n + 2] = a2; so[n + 3] = a3;
        } else {
            so[n] += a0; so[n + 1] += a1; so[n + 2] += a2; so[n + 3] += a3;
        }
    }
}

// ---------------------------------------------------------------------------
// generic fp32 SGEMM: C[M,N] = A[M,K] @ B[K,N], row-major, strided.
// BM=BN=128, BK=16, 256 threads, 8x8 microtile. M,N mult of 128; K mult of 16.
// flags bit0: relu applied to B elements on load
// flags bit1: C = relu(acc + bias[row])
// ---------------------------------------------------------------------------
__global__ __launch_bounds__(256) void k_sgemm(const float* __restrict__ A,
                                               const float* __restrict__ B,
                                               float* __restrict__ C,
                                               int M, int N, int K,
                                               int lda, int ldb, int ldc,
                                               const float* __restrict__ bias,
                                               int flags) {
    __shared__ float As[16][132];
    __shared__ float Bs[16][128];
    int tid = threadIdx.x;
    int m0 = blockIdx.y * 128, n0 = blockIdx.x * 128;
    int ty = tid >> 4, tx = tid & 15;

    float acc[8][8];
#pragma unroll
    for (int i = 0; i < 8; i++)
#pragma unroll
        for (int j = 0; j < 8; j++) acc[i][j] = 0.f;

    for (int k0 = 0; k0 < K; k0 += 16) {
#pragma unroll
        for (int i = 0; i < 2; i++) {
            int f = tid + i * 256;
            int r = f >> 2, kc = (f & 3) * 4;
            float4 v = *(const float4*)(A + (long)(m0 + r) * lda + k0 + kc);
            As[kc + 0][r] = v.x; As[kc + 1][r] = v.y;
            As[kc + 2][r] = v.z; As[kc + 3][r] = v.w;
        }
#pragma unroll
        for (int i = 0; i < 2; i++) {
            int f = tid + i * 256;
            int r = f >> 5, nc = (f & 31) * 4;
            float4 v = *(const float4*)(B + (long)(k0 + r) * ldb + n0 + nc);
            if (flags & 1) {
                v.x = fmaxf(v.x, 0.f); v.y = fmaxf(v.y, 0.f);
                v.z = fmaxf(v.z, 0.f); v.w = fmaxf(v.w, 0.f);
            }
            *(float4*)&Bs[r][nc] = v;
        }
        __syncthreads();
#pragma unroll
        for (int k = 0; k < 16; k++) {
            float a[8], b[8];
            float4 a0 = *(const float4*)&As[k][ty * 8];
            float4 a1 = *(const float4*)&As[k][ty * 8 + 4];
            a[0] = a0.x; a[1] = a0.y; a[2] = a0.z; a[3] = a0.w;
            a[4] = a1.x; a[5] = a1.y; a[6] = a1.z; a[7] = a1.w;
            float4 b0 = *(const float4*)&Bs[k][tx * 8];
            float4 b1 = *(const float4*)&Bs[k][tx * 8 + 4];
            b[0] = b0.x; b[1] = b0.y; b[2] = b0.z; b[3] = b0.w;
            b[4] = b1.x; b[5] = b1.y; b[6] = b1.z; b[7] = b1.w;
#pragma unroll
            for (int i = 0; i < 8; i++)
#pragma unroll
                for (int j = 0; j < 8; j++) acc[i][j] += a[i] * b[j];
        }
        __syncthreads();
    }

#pragma unroll
    for (int i = 0; i < 8; i++) {
        int mrow = m0 + ty * 8 + i;
        float bi = (flags & 2) ? bias[mrow] : 0.f;
        float4 o0, o1;
        if (flags & 2) {
            o0.x = fmaxf(acc[i][0] + bi, 0.f); o0.y = fmaxf(acc[i][1] + bi, 0.f);
            o0.z = fmaxf(acc[i][2] + bi, 0.f); o0.w = fmaxf(acc[i][3] + bi, 0.f);
            o1.x = fmaxf(acc[i][4] + bi, 0.f); o1.y = fmaxf(acc[i][5] + bi, 0.f);
            o1.z = fmaxf(acc[i][6] + bi, 0.f); o1.w = fmaxf(acc[i][7] + bi, 0.f);
        } else {
            o0.x = acc[i][0]; o0.y = acc[i][1]; o0.z = acc[i][2]; o0.w = acc[i][3];
            o1.x = acc[i][4]; o1.y = acc[i][5]; o1.z = acc[i][6]; o1.w = acc[i][7];
        }
        *(float4*)(C + (long)mrow * ldc + n0 + tx * 8) = o0;
        *(float4*)(C + (long)mrow * ldc + n0 + tx * 8 + 4) = o1;
    }
}

// ---------------------------------------------------------------------------
// gc mix + residual + BN:
// hnew[b][l][co][n] = ((Wm@m + W1@x1 + W2@x2 + gcb) + hold[b][l+d][co][n])*scale + shift
// grid: (64*L1, 16), 256 thr
// ---------------------------------------------------------------------------
__global__ __launch_bounds__(256) void k_gc(const float* __restrict__ m,
                                            const float* __restrict__ x12,
                                            const float* __restrict__ hold,
                                            const float* __restrict__ gcw,
                                            const float* __restrict__ gcb,
                                            const float* __restrict__ bng,
                                            const float* __restrict__ bnb,
                                            float* __restrict__ hnew,
                                            int L0, int L1, int d) {
    __shared__ float s_in[3][32][64];
    __shared__ float4 s_w[32][32];
    __shared__ float s_b[32], s_sc[32], s_sh[32];
    int bl = blockIdx.x;
    int b = bl / L1, l = bl - b * L1;
    int n0 = blockIdx.y * 64;
    int tid = threadIdx.x;
    for (int idx = tid; idx < 1024; idx += 256) {
        int co = idx >> 5, ci = idx & 31;
        s_w[co][ci] = make_float4(gcw[co * 96 + ci], gcw[co * 96 + 32 + ci],
                                  gcw[co * 96 + 64 + ci], 0.f);
    }
    if (tid < 32) {
        s_b[tid] = gcb[tid];
        s_sc[tid] = bng[tid] * rsqrtf(1.f + 1e-5f);
        s_sh[tid] = bnb[tid];
    }
    const float* mb = m + ((long)(b * L1 + l) * 32) * 1024 + n0;
    const float* xb = x12 + ((long)(b * L1 + l) * 32) * 2048 + n0;
    for (int idx = tid; idx < 2048; idx += 256) {
        int ci = idx >> 6, nl = idx & 63;
        s_in[0][ci][nl] = mb[(long)ci * 1024 + nl];
        s_in[1][ci][nl] = xb[(long)ci * 2048 + nl];
        s_in[2][ci][nl] = xb[(long)ci * 2048 + 1024 + nl];
    }
    __syncthreads();
    int nl = tid & 63, cg = tid >> 6;
    const float* rb = hold + ((long)(b * L0 + l + d) * 32) * 1024 + n0 + nl;
    float* ob = hnew + ((long)(b * L1 + l) * 32) * 1024 + n0 + nl;
#pragma unroll
    for (int u = 0; u < 8; u++) {
        int co = cg * 8 + u;
        float acc = s_b[co];
#pragma unroll
        for (int ci = 0; ci < 32; ci++) {
            float4 w = s_w[co][ci];
            acc += w.x * s_in[0][ci][nl] + w.y * s_in[1][ci][nl] + w.z * s_in[2][ci][nl];
        }
        float res = rb[(long)co * 1024];
        ob[(long)co * 1024] = (acc + res) * s_sc[co] + s_sh[co];
    }
}

// ---------------------------------------------------------------------------
// final projection: out[b][o][n] = sum_c W2[o][c]*e1[c][b*1024+n] + b2[o]
// grid: 256, 256 thr (thread == column)
// ---------------------------------------------------------------------------
__global__ __launch_bounds__(256) void k_end2(const float* __restrict__ e1,
                                              const float* __restrict__ w2,
                                              const float* __restrict__ b2,
                                              float* __restrict__ out) {
    __shared__ float s_w[12 * 512];
    int tid = threadIdx.x;
    for (int idx = tid; idx < 6144; idx += 256) s_w[idx] = w2[idx];
    __syncthreads();
    int col = blockIdx.x * 256 + tid;
    int b = col >> 10, n = col & 1023;
    float acc[12];
#pragma unroll
    for (int o = 0; o < 12; o++) acc[o] = b2[o];
    for (int c = 0; c < 512; c++) {
        float v = e1[(long)c * 65536 + col];
#pragma unroll
        for (int o = 0; o < 12; o++) acc[o] += s_w[o * 512 + c] * v;
    }
#pragma unroll
    for (int o = 0; o < 12; o++) out[((long)b * 12 + o) * 1024 + n] = acc[o];
}

// ---------------------------------------------------------------------------
extern "C" void kernel_launch(void* const* d_in, const int* in_sizes, int n_in,
                              void* d_out, int out_size) {
    const float* x        = (const float*)d_in[0];
    const float* start_w  = (const float*)d_in[1];
    const float* start_b  = (const float*)d_in[2];
    const float* nodevec1 = (const float*)d_in[3];
    const float* nodevec2 = (const float*)d_in[4];
    const float* filter_w = (const float*)d_in[5];
    const float* filter_b = (const float*)d_in[6];
    const float* gate_w   = (const float*)d_in[7];
    const float* gate_b   = (const float*)d_in[8];
    const float* skip_w   = (const float*)d_in[9];
    const float* skip_b   = (const float*)d_in[10];
    const float* gc_w     = (const float*)d_in[11];
    const float* gc_b     = (const float*)d_in[12];
    const float* bn_g     = (const float*)d_in[13];
    const float* bn_b     = (const float*)d_in[14];
    const float* end1_w   = (const float*)d_in[15];
    const float* end1_b   = (const float*)d_in[16];
    const float* end2_w   = (const float*)d_in[17];
    const float* end2_b   = (const float*)d_in[18];

    float *hA, *hB, *m, *x12, *Bm, *skip, *e1;
    cudaGetSymbolAddress((void**)&hA, g_hA);
    cudaGetSymbolAddress((void**)&hB, g_hB);
    cudaGetSymbolAddress((void**)&m, g_m);
    cudaGetSymbolAddress((void**)&x12, g_x12);
    cudaGetSymbolAddress((void**)&Bm, g_Bm);
    cudaGetSymbolAddress((void**)&skip, g_skip);
    cudaGetSymbolAddress((void**)&e1, g_e1);

    // adjacency + its square into fused B matrix [ADP | ADP^2]
    k_adp<<<1024, 256>>>(nodevec1, nodevec2, Bm);
    k_sgemm<<<dim3(8, 8), 256>>>(Bm, Bm, Bm + 1024, 1024, 1024, 1024,
                                 2048, 2048, 2048, nullptr, 0);
    // start conv (transposes x into [B][L][C][N])
    k_start<<<dim3(64 * 13, 4), 256>>>(x, start_w, start_b, hA);

    const int lens[9] = {13, 12, 10, 9, 7, 6, 4, 3, 1};
    const int dil[8]  = {1, 2, 1, 2, 1, 2, 1, 2};
    float* hcur = hA;
    float* hnext = hB;

    for (int i = 0; i < 8; i++) {
        int L0 = lens[i], L1 = lens[i + 1], d = dil[i];
        k_dconv<<<dim3(64 * L1, 16), 256>>>(hcur,
                                            filter_w + i * 2048, filter_b + i * 32,
                                            gate_w + i * 2048, gate_b + i * 32,
                                            m, L0, L1, d);
        k_skip<<<dim3(64, 8), 256>>>(m, skip_w + i * 256 * 32, skip_b + i * 256,
                                     skip, L1, i == 0 ? 1 : 0);
        if (i < 7) {
            int M = 2048 * L1;
            k_sgemm<<<dim3(2048 / 128, M / 128), 256>>>(m, Bm, x12, M, 2048, 1024,
                                                        1024, 2048, 2048, nullptr, 0);
            k_gc<<<dim3(64 * L1, 16), 256>>>(m, x12, hcur,
                                             gc_w + i * 32 * 96, gc_b + i * 32,
                                             bn_g + i * 32, bn_b + i * 32,
                                             hnext, L0, L1, d);
            float* t = hcur; hcur = hnext; hnext = t;
        }
    }

    // end: e1 = relu(end1_w @ relu(skip) + b1); out = end2_w @ e1 + b2
    k_sgemm<<<dim3(65536 / 128, 512 / 128), 256>>>(end1_w, skip, e1,
                                                   512, 65536, 256,
                                                   256, 65536, 65536, end1_b, 3);
    k_end2<<<256, 256>>>(e1, end2_w, end2_b, (float*)d_out);
}

// round 3
// speedup vs baseline: 1.6919x; 1.6919x over previous
#include <cuda_runtime.h>
#include <cuda_bf16.h>
#include <math.h>

// ---------------------------------------------------------------------------
// GWNet2: B=64, N=1024, L=13, RC=DC=32, SC=256, EC=512, OUT=12, LAYERS=8
// Internal layout for h/m/x: [B][L][C][N] (N innermost, contiguous rows of 1024)
// skip / e1 layout: [C][B*N]
// ---------------------------------------------------------------------------

// device scratch (allocation-free rule: __device__ globals)
__device__ float g_hA[64 * 13 * 32 * 1024];
__device__ float g_hB[64 * 12 * 32 * 1024];
__device__ float g_m [64 * 12 * 32 * 1024];
__device__ float g_x12[64 * 12 * 32 * 2048];  // (x1 | x2 per row)
__device__ float g_Bm[1024 * 2048];           // [ADP | ADP^2], row-major, ld=2048
__device__ float g_skip[256 * 64 * 1024];     // [C=256][B*N]
__device__ float g_e1 [512 * 64 * 1024];      // [C=512][B*N]

// ---------------------------------------------------------------------------
// adp = softmax(relu(nv1 @ nv2), axis=1); one block per row v
// ---------------------------------------------------------------------------
__global__ __launch_bounds__(256) void k_adp(const float* __restrict__ nv1,
                                             const float* __restrict__ nv2,
                                             float* __restrict__ Bm) {
    __shared__ float red[256];
    int v = blockIdx.x, tid = threadIdx.x;
    float n1[10];
#pragma unroll
    for (int k = 0; k < 10; k++) n1[k] = nv1[v * 10 + k];
    float a[4];
#pragma unroll
    for (int j = 0; j < 4; j++) {
        int w = tid + j * 256;
        float s = 0.f;
#pragma unroll
        for (int k = 0; k < 10; k++) s += n1[k] * nv2[k * 1024 + w];
        a[j] = fmaxf(s, 0.f);
    }
    float mx = fmaxf(fmaxf(a[0], a[1]), fmaxf(a[2], a[3]));
    red[tid] = mx; __syncthreads();
    for (int s = 128; s > 0; s >>= 1) {
        if (tid < s) red[tid] = fmaxf(red[tid], red[tid + s]);
        __syncthreads();
    }
    mx = red[0]; __syncthreads();
    float e[4]; float sum = 0.f;
#pragma unroll
    for (int j = 0; j < 4; j++) { e[j] = expf(a[j] - mx); sum += e[j]; }
    red[tid] = sum; __syncthreads();
    for (int s = 128; s > 0; s >>= 1) {
        if (tid < s) red[tid] += red[tid + s];
        __syncthreads();
    }
    float inv = 1.f / red[0];
#pragma unroll
    for (int j = 0; j < 4; j++) Bm[(long)v * 2048 + tid + j * 256] = e[j] * inv;
}

// ---------------------------------------------------------------------------
// start conv
// ---------------------------------------------------------------------------
__global__ __launch_bounds__(256) void k_start(const float* __restrict__ x,
                                               const float* __restrict__ sw,
                                               const float* __restrict__ sb,
                                               float* __restrict__ h) {
    int bl = blockIdx.x;
    int b = bl / 13, l = bl - b * 13;
    int n = blockIdx.y * 256 + threadIdx.x;
    float x0 = x[(((long)b * 2 + 0) * 1024 + n) * 13 + l];
    float x1 = x[(((long)b * 2 + 1) * 1024 + n) * 13 + l];
    float* hb = h + ((long)(b * 13 + l) * 32) * 1024 + n;
#pragma unroll
    for (int c = 0; c < 32; c++)
        hb[(long)c * 1024] = sw[c * 2] * x0 + sw[c * 2 + 1] * x1 + sb[c];
}

// ---------------------------------------------------------------------------
// dilated conv + tanh*sigmoid gate
// ---------------------------------------------------------------------------
__global__ __launch_bounds__(256) void k_dconv(const float* __restrict__ h,
                                               const float* __restrict__ fw,
                                               const float* __restrict__ fb,
                                               const float* __restrict__ gw,
                                               const float* __restrict__ gb,
                                               float* __restrict__ m,
                                               int L0, int L1, int d) {
    __shared__ float s_in[2][32][64];
    __shared__ float4 s_w[32][32];
    __shared__ float s_fb[32], s_gb[32];
    int bl = blockIdx.x;
    int b = bl / L1, l = bl - b * L1;
    int n0 = blockIdx.y * 64;
    int tid = threadIdx.x;
    for (int idx = tid; idx < 1024; idx += 256) {
        int co = idx >> 5, ci = idx & 31;
        int o = (co * 32 + ci) * 2;
        s_w[co][ci] = make_float4(fw[o], fw[o + 1], gw[o], gw[o + 1]);
    }
    if (tid < 32) { s_fb[tid] = fb[tid]; s_gb[tid] = gb[tid]; }
    const float* hb = h + ((long)(b * L0 + l) * 32) * 1024 + n0;
    for (int idx = tid; idx < 4096; idx += 256) {
        int tap = idx >> 11, ci = (idx >> 6) & 31, nl = idx & 63;
        s_in[tap][ci][nl] = hb[((long)(tap * d) * 32 + ci) * 1024 + nl];
    }
    __syncthreads();
    int nl = tid & 63, cg = tid >> 6;
    float* mo = m + ((long)(b * L1 + l) * 32) * 1024 + n0 + nl;
#pragma unroll
    for (int u = 0; u < 8; u++) {
        int co = cg * 8 + u;
        float fa = s_fb[co], ga = s_gb[co];
#pragma unroll
        for (int ci = 0; ci < 32; ci++) {
            float v0 = s_in[0][ci][nl], v1 = s_in[1][ci][nl];
            float4 w = s_w[co][ci];
            fa += w.x * v0 + w.y * v1;
            ga += w.z * v0 + w.w * v1;
        }
        mo[(long)co * 1024] = tanhf(fa) * (1.f / (1.f + expf(-ga)));
    }
}

// ---------------------------------------------------------------------------
// skip accumulation (last timestep only)
// ---------------------------------------------------------------------------
__global__ __launch_bounds__(256) void k_skip(const float* __restrict__ m,
                                              const float* __restrict__ sw,
                                              const float* __restrict__ sb,
                                              float* __restrict__ skip,
                                              int L1, int first) {
    __shared__ float s_m[32][128];
    int b = blockIdx.x;
    int n0 = blockIdx.y * 128;
    int tid = threadIdx.x;
    const float* mb = m + ((long)(b * L1 + (L1 - 1)) * 32) * 1024 + n0;
    for (int idx = tid; idx < 4096; idx += 256) {
        int ci = idx >> 7, nl = idx & 127;
        s_m[ci][nl] = mb[(long)ci * 1024 + nl];
    }
    __syncthreads();
    float w[32];
#pragma unroll
    for (int ci = 0; ci < 32; ci++) w[ci] = sw[tid * 32 + ci];
    float bias = sb[tid];
    float* so = skip + (long)tid * 65536 + b * 1024 + n0;
    for (int n = 0; n < 128; n += 4) {
        float a0 = bias, a1 = bias, a2 = bias, a3 = bias;
#pragma unroll
        for (int ci = 0; ci < 32; ci++) {
            float4 v = *(const float4*)&s_m[ci][n];
            a0 += w[ci] * v.x; a1 += w[ci] * v.y;
            a2 += w[ci] * v.z; a3 += w[ci] * v.w;
        }
        if (first) {
            so[n] = a0; so[n + 1] = a1; so[n + 2] = a2; so[n + 3] = a3;
        } else {
            so[n] += a0; so[n + 1] += a1; so[n + 2] += a2; so[n + 3] += a3;
        }
    }
}

// ---------------------------------------------------------------------------
// fp32 SIMT SGEMM (kept for ADP^2 only — full precision adjacency powers)
// ---------------------------------------------------------------------------
__global__ __launch_bounds__(256) void k_sgemm(const float* __restrict__ A,
                                               const float* __restrict__ B,
                                               float* __restrict__ C,
                                               int M, int N, int K,
                                               int lda, int ldb, int ldc) {
    __shared__ float As[16][132];
    __shared__ float Bs[16][128];
    int tid = threadIdx.x;
    int m0 = blockIdx.y * 128, n0 = blockIdx.x * 128;
    int ty = tid >> 4, tx = tid & 15;

    float acc[8][8];
#pragma unroll
    for (int i = 0; i < 8; i++)
#pragma unroll
        for (int j = 0; j < 8; j++) acc[i][j] = 0.f;

    for (int k0 = 0; k0 < K; k0 += 16) {
#pragma unroll
        for (int i = 0; i < 2; i++) {
            int f = tid + i * 256;
            int r = f >> 2, kc = (f & 3) * 4;
            float4 v = *(const float4*)(A + (long)(m0 + r) * lda + k0 + kc);
            As[kc + 0][r] = v.x; As[kc + 1][r] = v.y;
            As[kc + 2][r] = v.z; As[kc + 3][r] = v.w;
        }
#pragma unroll
        for (int i = 0; i < 2; i++) {
            int f = tid + i * 256;
            int r = f >> 5, nc = (f & 31) * 4;
            float4 v = *(const float4*)(B + (long)(k0 + r) * ldb + n0 + nc);
            *(float4*)&Bs[r][nc] = v;
        }
        __syncthreads();
#pragma unroll
        for (int k = 0; k < 16; k++) {
            float a[8], b[8];
            float4 a0 = *(const float4*)&As[k][ty * 8];
            float4 a1 = *(const float4*)&As[k][ty * 8 + 4];
            a[0] = a0.x; a[1] = a0.y; a[2] = a0.z; a[3] = a0.w;
            a[4] = a1.x; a[5] = a1.y; a[6] = a1.z; a[7] = a1.w;
            float4 b0 = *(const float4*)&Bs[k][tx * 8];
            float4 b1 = *(const float4*)&Bs[k][tx * 8 + 4];
            b[0] = b0.x; b[1] = b0.y; b[2] = b0.z; b[3] = b0.w;
            b[4] = b1.x; b[5] = b1.y; b[6] = b1.z; b[7] = b1.w;
#pragma unroll
            for (int i = 0; i < 8; i++)
#pragma unroll
                for (int j = 0; j < 8; j++) acc[i][j] += a[i] * b[j];
        }
        __syncthreads();
    }

#pragma unroll
    for (int i = 0; i < 8; i++) {
        int mrow = m0 + ty * 8 + i;
        *(float4*)(C + (long)mrow * ldc + n0 + tx * 8) =
            make_float4(acc[i][0], acc[i][1], acc[i][2], acc[i][3]);
        *(float4*)(C + (long)mrow * ldc + n0 + tx * 8 + 4) =
            make_float4(acc[i][4], acc[i][5], acc[i][6], acc[i][7]);
    }
}

// ---------------------------------------------------------------------------
// TF32 tensor-core GEMM: C[M,N] = A[M,K] @ B[K,N], row-major, strided.
// BM=BN=128, BK=32, 256 thr (8 warps, warp tile 32x64 via m16n8k8).
// flags bit0: relu on B load; bit1: C = relu(acc + bias[row])
// M,N mult of 128; K mult of 32.
// ---------------------------------------------------------------------------
__device__ __forceinline__ unsigned f2tf(float x) {
    unsigned r;
    asm("cvt.rna.tf32.f32 %0, %1;" : "=r"(r) : "f"(x));
    return r;
}

__global__ __launch_bounds__(256) void k_gemm_tf32(const float* __restrict__ A,
                                                   const float* __restrict__ B,
                                                   float* __restrict__ C,
                                                   int M, int N, int K,
                                                   int lda, int ldb, int ldc,
                                                   const float* __restrict__ bias,
                                                   int flags) {
    __shared__ unsigned As[128][36];   // [m][k], pad 36 -> conflict-free frag loads
    __shared__ unsigned Bs[32][136];   // [k][n], pad 136 -> conflict-free frag loads
    int tid = threadIdx.x;
    int m0 = blockIdx.y * 128, n0 = blockIdx.x * 128;
    int w = tid >> 5, lane = tid & 31;
    int grp = lane >> 2, tg = lane & 3;
    int wm = (w & 3) * 32, wn = (w >> 2) * 64;

    float acc[2][8][4];
#pragma unroll
    for (int mt = 0; mt < 2; mt++)
#pragma unroll
        for (int nt = 0; nt < 8; nt++)
#pragma unroll
            for (int c = 0; c < 4; c++) acc[mt][nt][c] = 0.f;

    for (int k0 = 0; k0 < K; k0 += 32) {
        // A tile: 128 rows x 32 k  (1024 float4)
#pragma unroll
        for (int i = 0; i < 4; i++) {
            int f = tid + i * 256;
            int r = f >> 3, c4 = (f & 7) * 4;
            float4 v = *(const float4*)(A + (long)(m0 + r) * lda + k0 + c4);
            As[r][c4 + 0] = f2tf(v.x); As[r][c4 + 1] = f2tf(v.y);
            As[r][c4 + 2] = f2tf(v.z); As[r][c4 + 3] = f2tf(v.w);
        }
        // B tile: 32 k x 128 cols (1024 float4)
#pragma unroll
        for (int i = 0; i < 4; i++) {
            int f = tid + i * 256;
            int r = f >> 5, c4 = (f & 31) * 4;
            float4 v = *(const float4*)(B + (long)(k0 + r) * ldb + n0 + c4);
            if (flags & 1) {
                v.x = fmaxf(v.x, 0.f); v.y = fmaxf(v.y, 0.f);
                v.z = fmaxf(v.z, 0.f); v.w = fmaxf(v.w, 0.f);
            }
            Bs[r][c4 + 0] = f2tf(v.x); Bs[r][c4 + 1] = f2tf(v.y);
            Bs[r][c4 + 2] = f2tf(v.z); Bs[r][c4 + 3] = f2tf(v.w);
        }
        __syncthreads();

#pragma unroll
        for (int ks = 0; ks < 4; ks++) {
            int k = ks * 8;
            unsigned a[2][4];
#pragma unroll
            for (int mt = 0; mt < 2; mt++) {
                int rb = wm + mt * 16;
                a[mt][0] = As[rb + grp][k + tg];
                a[mt][1] = As[rb + grp + 8][k + tg];
                a[mt][2] = As[rb + grp][k + tg + 4];
                a[mt][3] = As[rb + grp + 8][k + tg + 4];
            }
            unsigned b[8][2];
#pragma unroll
            for (int nt = 0; nt < 8; nt++) {
                int cb = wn + nt * 8 + grp;
                b[nt][0] = Bs[k + tg][cb];
                b[nt][1] = Bs[k + tg + 4][cb];
            }
#pragma unroll
            for (int mt = 0; mt < 2; mt++)
#pragma unroll
                for (int nt = 0; nt < 8; nt++) {
                    asm volatile(
                        "mma.sync.aligned.m16n8k8.row.col.f32.tf32.tf32.f32 "
                        "{%0,%1,%2,%3}, {%4,%5,%6,%7}, {%8,%9}, {%0,%1,%2,%3};\n"
                        : "+f"(acc[mt][nt][0]), "+f"(acc[mt][nt][1]),
                          "+f"(acc[mt][nt][2]), "+f"(acc[mt][nt][3])
                        : "r"(a[mt][0]), "r"(a[mt][1]), "r"(a[mt][2]), "r"(a[mt][3]),
                          "r"(b[nt][0]), "r"(b[nt][1]));
                }
        }
        __syncthreads();
    }

#pragma unroll
    for (int mt = 0; mt < 2; mt++) {
        int row0 = m0 + wm + mt * 16 + grp;
        int row1 = row0 + 8;
        float b0 = 0.f, b1 = 0.f;
        if (flags & 2) { b0 = bias[row0]; b1 = bias[row1]; }
#pragma unroll
        for (int nt = 0; nt < 8; nt++) {
            int col = n0 + wn + nt * 8 + tg * 2;
            float2 o0, o1;
            if (flags & 2) {
                o0.x = fmaxf(acc[mt][nt][0] + b0, 0.f);
                o0.y = fmaxf(acc[mt][nt][1] + b0, 0.f);
                o1.x = fmaxf(acc[mt][nt][2] + b1, 0.f);
                o1.y = fmaxf(acc[mt][nt][3] + b1, 0.f);
            } else {
                o0.x = acc[mt][nt][0]; o0.y = acc[mt][nt][1];
                o1.x = acc[mt][nt][2]; o1.y = acc[mt][nt][3];
            }
            *(float2*)(C + (long)row0 * ldc + col) = o0;
            *(float2*)(C + (long)row1 * ldc + col) = o1;
        }
    }
}

// ---------------------------------------------------------------------------
// gc mix + residual + BN
// ---------------------------------------------------------------------------
__global__ __launch_bounds__(256) void k_gc(const float* __restrict__ m,
                                            const float* __restrict__ x12,
                                            const float* __restrict__ hold,
                                            const float* __restrict__ gcw,
                                            const float* __restrict__ gcb,
                                            const float* __restrict__ bng,
                                            const float* __restrict__ bnb,
                                            float* __restrict__ hnew,
                                            int L0, int L1, int d) {
    __shared__ float s_in[3][32][64];
    __shared__ float4 s_w[32][32];
    __shared__ float s_b[32], s_sc[32], s_sh[32];
    int bl = blockIdx.x;
    int b = bl / L1, l = bl - b * L1;
    int n0 = blockIdx.y * 64;
    int tid = threadIdx.x;
    for (int idx = tid; idx < 1024; idx += 256) {
        int co = idx >> 5, ci = idx & 31;
        s_w[co][ci] = make_float4(gcw[co * 96 + ci], gcw[co * 96 + 32 + ci],
                                  gcw[co * 96 + 64 + ci], 0.f);
    }
    if (tid < 32) {
        s_b[tid] = gcb[tid];
        s_sc[tid] = bng[tid] * rsqrtf(1.f + 1e-5f);
        s_sh[tid] = bnb[tid];
    }
    const float* mb = m + ((long)(b * L1 + l) * 32) * 1024 + n0;
    const float* xb = x12 + ((long)(b * L1 + l) * 32) * 2048 + n0;
    for (int idx = tid; idx < 2048; idx += 256) {
        int ci = idx >> 6, nl = idx & 63;
        s_in[0][ci][nl] = mb[(long)ci * 1024 + nl];
        s_in[1][ci][nl] = xb[(long)ci * 2048 + nl];
        s_in[2][ci][nl] = xb[(long)ci * 2048 + 1024 + nl];
    }
    __syncthreads();
    int nl = tid & 63, cg = tid >> 6;
    const float* rb = hold + ((long)(b * L0 + l + d) * 32) * 1024 + n0 + nl;
    float* ob = hnew + ((long)(b * L1 + l) * 32) * 1024 + n0 + nl;
#pragma unroll
    for (int u = 0; u < 8; u++) {
        int co = cg * 8 + u;
        float acc = s_b[co];
#pragma unroll
        for (int ci = 0; ci < 32; ci++) {
            float4 w = s_w[co][ci];
            acc += w.x * s_in[0][ci][nl] + w.y * s_in[1][ci][nl] + w.z * s_in[2][ci][nl];
        }
        float res = rb[(long)co * 1024];
        ob[(long)co * 1024] = (acc + res) * s_sc[co] + s_sh[co];
    }
}

// ---------------------------------------------------------------------------
// final projection
// ---------------------------------------------------------------------------
__global__ __launch_bounds__(256) void k_end2(const float* __restrict__ e1,
                                              const float* __restrict__ w2,
                                              const float* __restrict__ b2,
                                              float* __restrict__ out) {
    __shared__ float s_w[12 * 512];
    int tid = threadIdx.x;
    for (int idx = tid; idx < 6144; idx += 256) s_w[idx] = w2[idx];
    __syncthreads();
    int col = blockIdx.x * 256 + tid;
    int b = col >> 10, n = col & 1023;
    float acc[12];
#pragma unroll
    for (int o = 0; o < 12; o++) acc[o] = b2[o];
    for (int c = 0; c < 512; c++) {
        float v = e1[(long)c * 65536 + col];
#pragma unroll
        for (int o = 0; o < 12; o++) acc[o] += s_w[o * 512 + c] * v;
    }
#pragma unroll
    for (int o = 0; o < 12; o++) out[((long)b * 12 + o) * 1024 + n] = acc[o];
}

// ---------------------------------------------------------------------------
extern "C" void kernel_launch(void* const* d_in, const int* in_sizes, int n_in,
                              void* d_out, int out_size) {
    const float* x        = (const float*)d_in[0];
    const float* start_w  = (const float*)d_in[1];
    const float* start_b  = (const float*)d_in[2];
    const float* nodevec1 = (const float*)d_in[3];
    const float* nodevec2 = (const float*)d_in[4];
    const float* filter_w = (const float*)d_in[5];
    const float* filter_b = (const float*)d_in[6];
    const float* gate_w   = (const float*)d_in[7];
    const float* gate_b   = (const float*)d_in[8];
    const float* skip_w   = (const float*)d_in[9];
    const float* skip_b   = (const float*)d_in[10];
    const float* gc_w     = (const float*)d_in[11];
    const float* gc_b     = (const float*)d_in[12];
    const float* bn_g     = (const float*)d_in[13];
    const float* bn_b     = (const float*)d_in[14];
    const float* end1_w   = (const float*)d_in[15];
    const float* end1_b   = (const float*)d_in[16];
    const float* end2_w   = (const float*)d_in[17];
    const float* end2_b   = (const float*)d_in[18];

    float *hA, *hB, *m, *x12, *Bm, *skip, *e1;
    cudaGetSymbolAddress((void**)&hA, g_hA);
    cudaGetSymbolAddress((void**)&hB, g_hB);
    cudaGetSymbolAddress((void**)&m, g_m);
    cudaGetSymbolAddress((void**)&x12, g_x12);
    cudaGetSymbolAddress((void**)&Bm, g_Bm);
    cudaGetSymbolAddress((void**)&skip, g_skip);
    cudaGetSymbolAddress((void**)&e1, g_e1);

    // adjacency + its square into fused B matrix [ADP | ADP^2] (fp32 for accuracy)
    k_adp<<<1024, 256>>>(nodevec1, nodevec2, Bm);
    k_sgemm<<<dim3(8, 8), 256>>>(Bm, Bm, Bm + 1024, 1024, 1024, 1024,
                                 2048, 2048, 2048);
    // start conv (transposes x into [B][L][C][N])
    k_start<<<dim3(64 * 13, 4), 256>>>(x, start_w, start_b, hA);

    const int lens[9] = {13, 12, 10, 9, 7, 6, 4, 3, 1};
    const int dil[8]  = {1, 2, 1, 2, 1, 2, 1, 2};
    float* hcur = hA;
    float* hnext = hB;

    for (int i = 0; i < 8; i++) {
        int L0 = lens[i], L1 = lens[i + 1], d = dil[i];
        k_dconv<<<dim3(64 * L1, 16), 256>>>(hcur,
                                            filter_w + i * 2048, filter_b + i * 32,
                                            gate_w + i * 2048, gate_b + i * 32,
                                            m, L0, L1, d);
        k_skip<<<dim3(64, 8), 256>>>(m, skip_w + i * 256 * 32, skip_b + i * 256,
                                     skip, L1, i == 0 ? 1 : 0);
        if (i < 7) {
            int M = 2048 * L1;
            // x12 = m @ [ADP | ADP^2]  — TF32 tensor cores
            k_gemm_tf32<<<dim3(2048 / 128, M / 128), 256>>>(
                m, Bm, x12, M, 2048, 1024, 1024, 2048, 2048, nullptr, 0);
            k_gc<<<dim3(64 * L1, 16), 256>>>(m, x12, hcur,
                                             gc_w + i * 32 * 96, gc_b + i * 32,
                                             bn_g + i * 32, bn_b + i * 32,
                                             hnext, L0, L1, d);
            float* t = hcur; hcur = hnext; hnext = t;
        }
    }

    // end: e1 = relu(end1_w @ relu(skip) + b1)  — TF32 tensor cores
    k_gemm_tf32<<<dim3(65536 / 128, 512 / 128), 256>>>(
        end1_w, skip, e1, 512, 65536, 256, 256, 65536, 65536, end1_b, 3);
    k_end2<<<256, 256>>>(e1, end2_w, end2_b, (float*)d_out);
}

// round 4
// speedup vs baseline: 1.8925x; 1.1186x over previous
#include <cuda_runtime.h>
#include <cuda_bf16.h>
#include <math.h>

// ---------------------------------------------------------------------------
// GWNet2: B=64, N=1024, L=13, RC=DC=32, SC=256, EC=512, OUT=12, LAYERS=8
// Internal layout for h/m/x: [B][L][C][N] (N innermost, rows of 1024)
// skip / e1 layout: [C][B*N]
// ---------------------------------------------------------------------------

__device__ float g_hA[64 * 13 * 32 * 1024];
__device__ float g_hB[64 * 12 * 32 * 1024];
__device__ float g_m [64 * 12 * 32 * 1024];
__device__ float g_x12[64 * 12 * 32 * 2048];  // (x1 | x2 per row)
__device__ float g_Bm[1024 * 2048];           // [ADP | ADP^2], ld=2048
__device__ float g_skip[256 * 64 * 1024];     // [C=256][B*N]
__device__ float g_e1 [512 * 64 * 1024];      // [C=512][B*N]

// ---------------------------------------------------------------------------
__global__ __launch_bounds__(256) void k_adp(const float* __restrict__ nv1,
                                             const float* __restrict__ nv2,
                                             float* __restrict__ Bm) {
    __shared__ float red[256];
    int v = blockIdx.x, tid = threadIdx.x;
    float n1[10];
#pragma unroll
    for (int k = 0; k < 10; k++) n1[k] = nv1[v * 10 + k];
    float a[4];
#pragma unroll
    for (int j = 0; j < 4; j++) {
        int w = tid + j * 256;
        float s = 0.f;
#pragma unroll
        for (int k = 0; k < 10; k++) s += n1[k] * nv2[k * 1024 + w];
        a[j] = fmaxf(s, 0.f);
    }
    float mx = fmaxf(fmaxf(a[0], a[1]), fmaxf(a[2], a[3]));
    red[tid] = mx; __syncthreads();
    for (int s = 128; s > 0; s >>= 1) {
        if (tid < s) red[tid] = fmaxf(red[tid], red[tid + s]);
        __syncthreads();
    }
    mx = red[0]; __syncthreads();
    float e[4]; float sum = 0.f;
#pragma unroll
    for (int j = 0; j < 4; j++) { e[j] = expf(a[j] - mx); sum += e[j]; }
    red[tid] = sum; __syncthreads();
    for (int s = 128; s > 0; s >>= 1) {
        if (tid < s) red[tid] += red[tid + s];
        __syncthreads();
    }
    float inv = 1.f / red[0];
#pragma unroll
    for (int j = 0; j < 4; j++) Bm[(long)v * 2048 + tid + j * 256] = e[j] * inv;
}

// ---------------------------------------------------------------------------
__global__ __launch_bounds__(256) void k_start(const float* __restrict__ x,
                                               const float* __restrict__ sw,
                                               const float* __restrict__ sb,
                                               float* __restrict__ h) {
    int bl = blockIdx.x;
    int b = bl / 13, l = bl - b * 13;
    int n = blockIdx.y * 256 + threadIdx.x;
    float x0 = x[(((long)b * 2 + 0) * 1024 + n) * 13 + l];
    float x1 = x[(((long)b * 2 + 1) * 1024 + n) * 13 + l];
    float* hb = h + ((long)(b * 13 + l) * 32) * 1024 + n;
#pragma unroll
    for (int c = 0; c < 32; c++)
        hb[(long)c * 1024] = sw[c * 2] * x0 + sw[c * 2 + 1] * x1 + sb[c];
}

// ---------------------------------------------------------------------------
// dilated conv + tanh*sigmoid gate. Loop order: ci outer, 8 co-accumulators
// in registers -> s_in read once per ci (was 8x).
// ---------------------------------------------------------------------------
__global__ __launch_bounds__(256) void k_dconv(const float* __restrict__ h,
                                               const float* __restrict__ fw,
                                               const float* __restrict__ fb,
                                               const float* __restrict__ gw,
                                               const float* __restrict__ gb,
                                               float* __restrict__ m,
                                               int L0, int L1, int d) {
    __shared__ float s_in[2][32][64];
    __shared__ float4 s_w[32][32];
    __shared__ float s_fb[32], s_gb[32];
    int bl = blockIdx.x;
    int b = bl / L1, l = bl - b * L1;
    int n0 = blockIdx.y * 64;
    int tid = threadIdx.x;
    for (int idx = tid; idx < 1024; idx += 256) {
        int co = idx >> 5, ci = idx & 31;
        int o = (co * 32 + ci) * 2;
        s_w[co][ci] = make_float4(fw[o], fw[o + 1], gw[o], gw[o + 1]);
    }
    if (tid < 32) { s_fb[tid] = fb[tid]; s_gb[tid] = gb[tid]; }
    const float* hb = h + ((long)(b * L0 + l) * 32) * 1024 + n0;
    for (int idx = tid; idx < 4096; idx += 256) {
        int tap = idx >> 11, ci = (idx >> 6) & 31, nl = idx & 63;
        s_in[tap][ci][nl] = hb[((long)(tap * d) * 32 + ci) * 1024 + nl];
    }
    __syncthreads();
    int nl = tid & 63, cg = tid >> 6;
    float fa[8], ga[8];
#pragma unroll
    for (int u = 0; u < 8; u++) { fa[u] = s_fb[cg * 8 + u]; ga[u] = s_gb[cg * 8 + u]; }
#pragma unroll
    for (int ci = 0; ci < 32; ci++) {
        float v0 = s_in[0][ci][nl], v1 = s_in[1][ci][nl];
#pragma unroll
        for (int u = 0; u < 8; u++) {
            float4 w = s_w[cg * 8 + u][ci];
            fa[u] += w.x * v0 + w.y * v1;
            ga[u] += w.z * v0 + w.w * v1;
        }
    }
    float* mo = m + ((long)(b * L1 + l) * 32) * 1024 + n0 + nl;
#pragma unroll
    for (int u = 0; u < 8; u++)
        mo[(long)(cg * 8 + u) * 1024] = tanhf(fa[u]) * (1.f / (1.f + expf(-ga[u])));
}

// ---------------------------------------------------------------------------
__global__ __launch_bounds__(256) void k_skip(const float* __restrict__ m,
                                              const float* __restrict__ sw,
                                              const float* __restrict__ sb,
                                              float* __restrict__ skip,
                                              int L1, int first) {
    __shared__ float s_m[32][128];
    int b = blockIdx.x;
    int n0 = blockIdx.y * 128;
    int tid = threadIdx.x;
    const float* mb = m + ((long)(b * L1 + (L1 - 1)) * 32) * 1024 + n0;
    for (int idx = tid; idx < 4096; idx += 256) {
        int ci = idx >> 7, nl = idx & 127;
        s_m[ci][nl] = mb[(long)ci * 1024 + nl];
    }
    __syncthreads();
    float w[32];
#pragma unroll
    for (int ci = 0; ci < 32; ci++) w[ci] = sw[tid * 32 + ci];
    float bias = sb[tid];
    float* so = skip + (long)tid * 65536 + b * 1024 + n0;
    for (int n = 0; n < 128; n += 4) {
        float a0 = bias, a1 = bias, a2 = bias, a3 = bias;
#pragma unroll
        for (int ci = 0; ci < 32; ci++) {
            float4 v = *(const float4*)&s_m[ci][n];
            a0 += w[ci] * v.x; a1 += w[ci] * v.y;
            a2 += w[ci] * v.z; a3 += w[ci] * v.w;
        }
        if (first) {
            so[n] = a0; so[n + 1] = a1; so[n + 2] = a2; so[n + 3] = a3;
        } else {
            so[n] += a0; so[n + 1] += a1; so[n + 2] += a2; so[n + 3] += a3;
        }
    }
}

// ---------------------------------------------------------------------------
// fp32 SIMT SGEMM (ADP^2 only)
// ---------------------------------------------------------------------------
__global__ __launch_bounds__(256) void k_sgemm(const float* __restrict__ A,
                                               const float* __restrict__ B,
                                               float* __restrict__ C,
                                               int M, int N, int K,
                                               int lda, int ldb, int ldc) {
    __shared__ float As[16][132];
    __shared__ float Bs[16][128];
    int tid = threadIdx.x;
    int m0 = blockIdx.y * 128, n0 = blockIdx.x * 128;
    int ty = tid >> 4, tx = tid & 15;

    float acc[8][8];
#pragma unroll
    for (int i = 0; i < 8; i++)
#pragma unroll
        for (int j = 0; j < 8; j++) acc[i][j] = 0.f;

    for (int k0 = 0; k0 < K; k0 += 16) {
#pragma unroll
        for (int i = 0; i < 2; i++) {
            int f = tid + i * 256;
            int r = f >> 2, kc = (f & 3) * 4;
            float4 v = *(const float4*)(A + (long)(m0 + r) * lda + k0 + kc);
            As[kc + 0][r] = v.x; As[kc + 1][r] = v.y;
            As[kc + 2][r] = v.z; As[kc + 3][r] = v.w;
        }
#pragma unroll
        for (int i = 0; i < 2; i++) {
            int f = tid + i * 256;
            int r = f >> 5, nc = (f & 31) * 4;
            float4 v = *(const float4*)(B + (long)(k0 + r) * ldb + n0 + nc);
            *(float4*)&Bs[r][nc] = v;
        }
        __syncthreads();
#pragma unroll
        for (int k = 0; k < 16; k++) {
            float a[8], b[8];
            float4 a0 = *(const float4*)&As[k][ty * 8];
            float4 a1 = *(const float4*)&As[k][ty * 8 + 4];
            a[0] = a0.x; a[1] = a0.y; a[2] = a0.z; a[3] = a0.w;
            a[4] = a1.x; a[5] = a1.y; a[6] = a1.z; a[7] = a1.w;
            float4 b0 = *(const float4*)&Bs[k][tx * 8];
            float4 b1 = *(const float4*)&Bs[k][tx * 8 + 4];
            b[0] = b0.x; b[1] = b0.y; b[2] = b0.z; b[3] = b0.w;
            b[4] = b1.x; b[5] = b1.y; b[6] = b1.z; b[7] = b1.w;
#pragma unroll
            for (int i = 0; i < 8; i++)
#pragma unroll
                for (int j = 0; j < 8; j++) acc[i][j] += a[i] * b[j];
        }
        __syncthreads();
    }

#pragma unroll
    for (int i = 0; i < 8; i++) {
        int mrow = m0 + ty * 8 + i;
        *(float4*)(C + (long)mrow * ldc + n0 + tx * 8) =
            make_float4(acc[i][0], acc[i][1], acc[i][2], acc[i][3]);
        *(float4*)(C + (long)mrow * ldc + n0 + tx * 8 + 4) =
            make_float4(acc[i][4], acc[i][5], acc[i][6], acc[i][7]);
    }
}

// ---------------------------------------------------------------------------
// TF32 tensor-core GEMM, cp.async double-buffered.
// C[M,N] = A[M,K] @ B[K,N] row-major strided. BM=BN=128, BK=32, 256 thr.
// flags bit0: relu on B; bit1: C = relu(acc + bias[row]).
// ---------------------------------------------------------------------------
__device__ __forceinline__ unsigned f2tf(float x) {
    unsigned r;
    asm("cvt.rna.tf32.f32 %0, %1;" : "=r"(r) : "f"(x));
    return r;
}
__device__ __forceinline__ void cp16(void* smem, const void* g) {
    unsigned s = (unsigned)__cvta_generic_to_shared(smem);
    asm volatile("cp.async.cg.shared.global [%0], [%1], 16;\n" :: "r"(s), "l"(g));
}

__global__ __launch_bounds__(256) void k_gemm_tf32(const float* __restrict__ A,
                                                   const float* __restrict__ B,
                                                   float* __restrict__ C,
                                                   int M, int N, int K,
                                                   int lda, int ldb, int ldc,
                                                   const float* __restrict__ bias,
                                                   int flags) {
    __shared__ float As[2][128][36];   // [m][k], pad 36
    __shared__ float Bs[2][32][136];   // [k][n], pad 136
    int tid = threadIdx.x;
    int m0 = blockIdx.y * 128, n0 = blockIdx.x * 128;
    int w = tid >> 5, lane = tid & 31;
    int grp = lane >> 2, tg = lane & 3;
    int wm = (w & 3) * 32, wn = (w >> 2) * 64;

    // per-thread load coords
    int ar = tid >> 1, ac = (tid & 1) * 16;            // A: 128 rows x 32 cols, 2 float4/row pair
    int br = tid >> 3, bc = (tid & 7) * 16;            // B: 32 rows x 128 cols

    float acc[2][8][4];
#pragma unroll
    for (int mt = 0; mt < 2; mt++)
#pragma unroll
        for (int nt = 0; nt < 8; nt++)
#pragma unroll
            for (int c = 0; c < 4; c++) acc[mt][nt][c] = 0.f;

    int nstage = K / 32;
    // prefetch stage 0
    {
        const float* ag = A + (long)(m0 + ar) * lda + ac;
        cp16(&As[0][ar][ac], ag);
        cp16(&As[0][ar][ac + 4], ag + 4);
        cp16(&As[0][ar][ac + 8], ag + 8);
        cp16(&As[0][ar][ac + 12], ag + 12);
        const float* bg = B + (long)br * ldb + n0 + bc;
        cp16(&Bs[0][br][bc], bg);
        cp16(&Bs[0][br][bc + 4], bg + 4);
        cp16(&Bs[0][br][bc + 8], bg + 8);
        cp16(&Bs[0][br][bc + 12], bg + 12);
        asm volatile("cp.async.commit_group;\n");
    }

    for (int s = 0; s < nstage; s++) {
        int buf = s & 1;
        if (s + 1 < nstage) {
            int nb = buf ^ 1;
            int k0 = (s + 1) * 32;
            const float* ag = A + (long)(m0 + ar) * lda + k0 + ac;
            cp16(&As[nb][ar][ac], ag);
            cp16(&As[nb][ar][ac + 4], ag + 4);
            cp16(&As[nb][ar][ac + 8], ag + 8);
            cp16(&As[nb][ar][ac + 12], ag + 12);
            const float* bg = B + (long)(k0 + br) * ldb + n0 + bc;
            cp16(&Bs[nb][br][bc], bg);
            cp16(&Bs[nb][br][bc + 4], bg + 4);
            cp16(&Bs[nb][br][bc + 8], bg + 8);
            cp16(&Bs[nb][br][bc + 12], bg + 12);
            asm volatile("cp.async.commit_group;\n");
            asm volatile("cp.async.wait_group 1;\n");
        } else {
            asm volatile("cp.async.wait_group 0;\n");
        }
        __syncthreads();

#pragma unroll
        for (int ks = 0; ks < 4; ks++) {
            int k = ks * 8;
            unsigned a[2][4];
#pragma unroll
            for (int mt = 0; mt < 2; mt++) {
                int rb = wm + mt * 16;
                a[mt][0] = f2tf(As[buf][rb + grp][k + tg]);
                a[mt][1] = f2tf(As[buf][rb + grp + 8][k + tg]);
                a[mt][2] = f2tf(As[buf][rb + grp][k + tg + 4]);
                a[mt][3] = f2tf(As[buf][rb + grp + 8][k + tg + 4]);
            }
            unsigned b[8][2];
#pragma unroll
            for (int nt = 0; nt < 8; nt++) {
                int cb = wn + nt * 8 + grp;
                float b0 = Bs[buf][k + tg][cb];
                float b1 = Bs[buf][k + tg + 4][cb];
                if (flags & 1) { b0 = fmaxf(b0, 0.f); b1 = fmaxf(b1, 0.f); }
                b[nt][0] = f2tf(b0);
                b[nt][1] = f2tf(b1);
            }
#pragma unroll
            for (int mt = 0; mt < 2; mt++)
#pragma unroll
                for (int nt = 0; nt < 8; nt++) {
                    asm volatile(
                        "mma.sync.aligned.m16n8k8.row.col.f32.tf32.tf32.f32 "
                        "{%0,%1,%2,%3}, {%4,%5,%6,%7}, {%8,%9}, {%0,%1,%2,%3};\n"
                        : "+f"(acc[mt][nt][0]), "+f"(acc[mt][nt][1]),
                          "+f"(acc[mt][nt][2]), "+f"(acc[mt][nt][3])
                        : "r"(a[mt][0]), "r"(a[mt][1]), "r"(a[mt][2]), "r"(a[mt][3]),
                          "r"(b[nt][0]), "r"(b[nt][1]));
                }
        }
        __syncthreads();
    }

#pragma unroll
    for (int mt = 0; mt < 2; mt++) {
        int row0 = m0 + wm + mt * 16 + grp;
        int row1 = row0 + 8;
        float b0 = 0.f, b1 = 0.f;
        if (flags & 2) { b0 = bias[row0]; b1 = bias[row1]; }
#pragma unroll
        for (int nt = 0; nt < 8; nt++) {
            int col = n0 + wn + nt * 8 + tg * 2;
            float2 o0, o1;
            if (flags & 2) {
                o0.x = fmaxf(acc[mt][nt][0] + b0, 0.f);
                o0.y = fmaxf(acc[mt][nt][1] + b0, 0.f);
                o1.x = fmaxf(acc[mt][nt][2] + b1, 0.f);
                o1.y = fmaxf(acc[mt][nt][3] + b1, 0.f);
            } else {
                o0.x = acc[mt][nt][0]; o0.y = acc[mt][nt][1];
                o1.x = acc[mt][nt][2]; o1.y = acc[mt][nt][3];
            }
            *(float2*)(C + (long)row0 * ldc + col) = o0;
            *(float2*)(C + (long)row1 * ldc + col) = o1;
        }
    }
}

// ---------------------------------------------------------------------------
// gc mix + residual + BN. Loop-swapped like k_dconv.
// ---------------------------------------------------------------------------
__global__ __launch_bounds__(256) void k_gc(const float* __restrict__ m,
                                            const float* __restrict__ x12,
                                            const float* __restrict__ hold,
                                            const float* __restrict__ gcw,
                                            const float* __restrict__ gcb,
                                            const float* __restrict__ bng,
                                            const float* __restrict__ bnb,
                                            float* __restrict__ hnew,
                                            int L0, int L1, int d) {
    __shared__ float s_in[3][32][64];
    __shared__ float4 s_w[32][32];
    __shared__ float s_b[32], s_sc[32], s_sh[32];
    int bl = blockIdx.x;
    int b = bl / L1, l = bl - b * L1;
    int n0 = blockIdx.y * 64;
    int tid = threadIdx.x;
    for (int idx = tid; idx < 1024; idx += 256) {
        int co = idx >> 5, ci = idx & 31;
        s_w[co][ci] = make_float4(gcw[co * 96 + ci], gcw[co * 96 + 32 + ci],
                                  gcw[co * 96 + 64 + ci], 0.f);
    }
    if (tid < 32) {
        s_b[tid] = gcb[tid];
        s_sc[tid] = bng[tid] * rsqrtf(1.f + 1e-5f);
        s_sh[tid] = bnb[tid];
    }
    const float* mb = m + ((long)(b * L1 + l) * 32) * 1024 + n0;
    const float* xb = x12 + ((long)(b * L1 + l) * 32) * 2048 + n0;
    for (int idx = tid; idx < 2048; idx += 256) {
        int ci = idx >> 6, nl = idx & 63;
        s_in[0][ci][nl] = mb[(long)ci * 1024 + nl];
        s_in[1][ci][nl] = xb[(long)ci * 2048 + nl];
        s_in[2][ci][nl] = xb[(long)ci * 2048 + 1024 + nl];
    }
    __syncthreads();
    int nl = tid & 63, cg = tid >> 6;
    float acc[8];
#pragma unroll
    for (int u = 0; u < 8; u++) acc[u] = s_b[cg * 8 + u];
#pragma unroll
    for (int ci = 0; ci < 32; ci++) {
        float v0 = s_in[0][ci][nl], v1 = s_in[1][ci][nl], v2 = s_in[2][ci][nl];
#pragma unroll
        for (int u = 0; u < 8; u++) {
            float4 w = s_w[cg * 8 + u][ci];
            acc[u] += w.x * v0 + w.y * v1 + w.z * v2;
        }
    }
    const float* rb = hold + ((long)(b * L0 + l + d) * 32) * 1024 + n0 + nl;
    float* ob = hnew + ((long)(b * L1 + l) * 32) * 1024 + n0 + nl;
#pragma unroll
    for (int u = 0; u < 8; u++) {
        int co = cg * 8 + u;
        float res = rb[(long)co * 1024];
        ob[(long)co * 1024] = (acc[u] + res) * s_sc[co] + s_sh[co];
    }
}

// ---------------------------------------------------------------------------
__global__ __launch_bounds__(256) void k_end2(const float* __restrict__ e1,
                                              const float* __restrict__ w2,
                                              const float* __restrict__ b2,
                                              float* __restrict__ out) {
    __shared__ float s_w[12 * 512];
    int tid = threadIdx.x;
    for (int idx = tid; idx < 6144; idx += 256) s_w[idx] = w2[idx];
    __syncthreads();
    int col = blockIdx.x * 256 + tid;
    int b = col >> 10, n = col & 1023;
    float acc[12];
#pragma unroll
    for (int o = 0; o < 12; o++) acc[o] = b2[o];
    for (int c = 0; c < 512; c++) {
        float v = e1[(long)c * 65536 + col];
#pragma unroll
        for (int o = 0; o < 12; o++) acc[o] += s_w[o * 512 + c] * v;
    }
#pragma unroll
    for (int o = 0; o < 12; o++) out[((long)b * 12 + o) * 1024 + n] = acc[o];
}

// ---------------------------------------------------------------------------
extern "C" void kernel_launch(void* const* d_in, const int* in_sizes, int n_in,
                              void* d_out, int out_size) {
    const float* x        = (const float*)d_in[0];
    const float* start_w  = (const float*)d_in[1];
    const float* start_b  = (const float*)d_in[2];
    const float* nodevec1 = (const float*)d_in[3];
    const float* nodevec2 = (const float*)d_in[4];
    const float* filter_w = (const float*)d_in[5];
    const float* filter_b = (const float*)d_in[6];
    const float* gate_w   = (const float*)d_in[7];
    const float* gate_b   = (const float*)d_in[8];
    const float* skip_w   = (const float*)d_in[9];
    const float* skip_b   = (const float*)d_in[10];
    const float* gc_w     = (const float*)d_in[11];
    const float* gc_b     = (const float*)d_in[12];
    const float* bn_g     = (const float*)d_in[13];
    const float* bn_b     = (const float*)d_in[14];
    const float* end1_w   = (const float*)d_in[15];
    const float* end1_b   = (const float*)d_in[16];
    const float* end2_w   = (const float*)d_in[17];
    const float* end2_b   = (const float*)d_in[18];

    float *hA, *hB, *m, *x12, *Bm, *skip, *e1;
    cudaGetSymbolAddress((void**)&hA, g_hA);
    cudaGetSymbolAddress((void**)&hB, g_hB);
    cudaGetSymbolAddress((void**)&m, g_m);
    cudaGetSymbolAddress((void**)&x12, g_x12);
    cudaGetSymbolAddress((void**)&Bm, g_Bm);
    cudaGetSymbolAddress((void**)&skip, g_skip);
    cudaGetSymbolAddress((void**)&e1, g_e1);

    k_adp<<<1024, 256>>>(nodevec1, nodevec2, Bm);
    k_sgemm<<<dim3(8, 8), 256>>>(Bm, Bm, Bm + 1024, 1024, 1024, 1024,
                                 2048, 2048, 2048);
    k_start<<<dim3(64 * 13, 4), 256>>>(x, start_w, start_b, hA);

    const int lens[9] = {13, 12, 10, 9, 7, 6, 4, 3, 1};
    const int dil[8]  = {1, 2, 1, 2, 1, 2, 1, 2};
    float* hcur = hA;
    float* hnext = hB;

    for (int i = 0; i < 8; i++) {
        int L0 = lens[i], L1 = lens[i + 1], d = dil[i];
        k_dconv<<<dim3(64 * L1, 16), 256>>>(hcur,
                                            filter_w + i * 2048, filter_b + i * 32,
                                            gate_w + i * 2048, gate_b + i * 32,
                                            m, L0, L1, d);
        k_skip<<<dim3(64, 8), 256>>>(m, skip_w + i * 256 * 32, skip_b + i * 256,
                                     skip, L1, i == 0 ? 1 : 0);
        if (i < 7) {
            int M = 2048 * L1;
            k_gemm_tf32<<<dim3(2048 / 128, M / 128), 256>>>(
                m, Bm, x12, M, 2048, 1024, 1024, 2048, 2048, nullptr, 0);
            k_gc<<<dim3(64 * L1, 16), 256>>>(m, x12, hcur,
                                             gc_w + i * 32 * 96, gc_b + i * 32,
                                             bn_g + i * 32, bn_b + i * 32,
                                             hnext, L0, L1, d);
            float* t = hcur; hcur = hnext; hnext = t;
        }
    }

    k_gemm_tf32<<<dim3(65536 / 128, 512 / 128), 256>>>(
        end1_w, skip, e1, 512, 65536, 256, 256, 65536, 65536, end1_b, 3);
    k_end2<<<256, 256>>>(e1, end2_w, end2_b, (float*)d_out);
}

// round 6
// speedup vs baseline: 2.2598x; 1.1941x over previous
#include <cuda_runtime.h>
#include <cuda_bf16.h>
#include <math.h>
#include <stdint.h>

// ---------------------------------------------------------------------------
// GWNet2: B=64, N=1024, L=13, RC=DC=32, SC=256, EC=512, OUT=12, LAYERS=8
// h/m/x layout: [B][L][C][N] (N innermost). skip/e1/msk: [C][B*N].
// All GEMMs on mma.sync tf32 (operands pre-rounded; no in-loop cvt).
// ---------------------------------------------------------------------------

__device__ float g_hA [64 * 13 * 32 * 1024];
__device__ float g_hB [64 * 12 * 32 * 1024];
__device__ float g_m  [64 * 12 * 32 * 1024];
__device__ float g_x12[64 * 12 * 32 * 2048];   // (x1 | x2)
__device__ float g_Bm [1024 * 2048];           // [ADP | ADP^2], ld=2048, tf32-rounded
__device__ float g_msk[256 * 64 * 1024];       // concat of per-layer m last timestep
__device__ float g_skip[256 * 64 * 1024];      // relu(skip), [C=256][B*N]
__device__ float g_e1 [512 * 64 * 1024];       // [C=512][B*N]
__device__ float g_w1r [512 * 256];            // end1_w tf32-rounded
__device__ float g_wsk [256 * 256];            // concat skip weights, tf32-rounded
__device__ float g_bsk [256];                  // summed skip bias

// ---------------------------------------------------------------------------
__device__ __forceinline__ float tf32r(float x) {
    unsigned u;
    asm("cvt.rna.tf32.f32 %0, %1;" : "=r"(u) : "f"(x));
    return __uint_as_float(u);
}
__device__ __forceinline__ void cp16(void* smem, const void* g) {
    unsigned s = (unsigned)__cvta_generic_to_shared(smem);
    asm volatile("cp.async.cg.shared.global [%0], [%1], 16;\n" :: "r"(s), "l"(g));
}

// ---------------------------------------------------------------------------
// adp = softmax(relu(nv1 @ nv2), axis=1), tf32-rounded into Bm cols 0..1023
// ---------------------------------------------------------------------------
__global__ __launch_bounds__(256) void k_adp(const float* __restrict__ nv1,
                                             const float* __restrict__ nv2,
                                             float* __restrict__ Bm) {
    __shared__ float red[256];
    int v = blockIdx.x, tid = threadIdx.x;
    float n1[10];
#pragma unroll
    for (int k = 0; k < 10; k++) n1[k] = nv1[v * 10 + k];
    float a[4];
#pragma unroll
    for (int j = 0; j < 4; j++) {
        int w = tid + j * 256;
        float s = 0.f;
#pragma unroll
        for (int k = 0; k < 10; k++) s += n1[k] * nv2[k * 1024 + w];
        a[j] = fmaxf(s, 0.f);
    }
    float mx = fmaxf(fmaxf(a[0], a[1]), fmaxf(a[2], a[3]));
    red[tid] = mx; __syncthreads();
    for (int s = 128; s > 0; s >>= 1) {
        if (tid < s) red[tid] = fmaxf(red[tid], red[tid + s]);
        __syncthreads();
    }
    mx = red[0]; __syncthreads();
    float e[4]; float sum = 0.f;
#pragma unroll
    for (int j = 0; j < 4; j++) { e[j] = expf(a[j] - mx); sum += e[j]; }
    red[tid] = sum; __syncthreads();
    for (int s = 128; s > 0; s >>= 1) {
        if (tid < s) red[tid] += red[tid + s];
        __syncthreads();
    }
    float inv = 1.f / red[0];
#pragma unroll
    for (int j = 0; j < 4; j++)
        Bm[(long)v * 2048 + tid + j * 256] = tf32r(e[j] * inv);
}

// ---------------------------------------------------------------------------
__global__ __launch_bounds__(256) void k_start(const float* __restrict__ x,
                                               const float* __restrict__ sw,
                                               const float* __restrict__ sb,
                                               float* __restrict__ h) {
    int bl = blockIdx.x;
    int b = bl / 13, l = bl - b * 13;
    int n = blockIdx.y * 256 + threadIdx.x;
    float x0 = x[(((long)b * 2 + 0) * 1024 + n) * 13 + l];
    float x1 = x[(((long)b * 2 + 1) * 1024 + n) * 13 + l];
    float* hb = h + ((long)(b * 13 + l) * 32) * 1024 + n;
#pragma unroll
    for (int c = 0; c < 32; c++)
        hb[(long)c * 1024] = sw[c * 2] * x0 + sw[c * 2 + 1] * x1 + sb[c];
}

// ---------------------------------------------------------------------------
// dilated conv + tanh*sigmoid; output tf32-rounded. Last timestep also goes
// into msk[layer*32+co][b*1024+n] for the fused skip GEMM.
// ---------------------------------------------------------------------------
__global__ __launch_bounds__(256) void k_dconv(const float* __restrict__ h,
                                               const float* __restrict__ fw,
                                               const float* __restrict__ fb,
                                               const float* __restrict__ gw,
                                               const float* __restrict__ gb,
                                               float* __restrict__ m,
                                               float* __restrict__ msk,
                                               int L0, int L1, int d, int layer) {
    __shared__ float s_in[2][32][64];
    __shared__ float4 s_w[32][32];
    __shared__ float s_fb[32], s_gb[32];
    int bl = blockIdx.x;
    int b = bl / L1, l = bl - b * L1;
    int n0 = blockIdx.y * 64;
    int tid = threadIdx.x;
    for (int idx = tid; idx < 1024; idx += 256) {
        int co = idx >> 5, ci = idx & 31;
        int o = (co * 32 + ci) * 2;
        s_w[co][ci] = make_float4(fw[o], fw[o + 1], gw[o], gw[o + 1]);
    }
    if (tid < 32) { s_fb[tid] = fb[tid]; s_gb[tid] = gb[tid]; }
    const float* hb = h + ((long)(b * L0 + l) * 32) * 1024 + n0;
    for (int idx = tid; idx < 4096; idx += 256) {
        int tap = idx >> 11, ci = (idx >> 6) & 31, nl = idx & 63;
        s_in[tap][ci][nl] = hb[((long)(tap * d) * 32 + ci) * 1024 + nl];
    }
    __syncthreads();
    int nl = tid & 63, cg = tid >> 6;
    float fa[8], ga[8];
#pragma unroll
    for (int u = 0; u < 8; u++) { fa[u] = s_fb[cg * 8 + u]; ga[u] = s_gb[cg * 8 + u]; }
#pragma unroll
    for (int ci = 0; ci < 32; ci++) {
        float v0 = s_in[0][ci][nl], v1 = s_in[1][ci][nl];
#pragma unroll
        for (int u = 0; u < 8; u++) {
            float4 w = s_w[cg * 8 + u][ci];
            fa[u] += w.x * v0 + w.y * v1;
            ga[u] += w.z * v0 + w.w * v1;
        }
    }
    float* mo = m + ((long)(b * L1 + l) * 32) * 1024 + n0 + nl;
    bool last = (l == L1 - 1);
#pragma unroll
    for (int u = 0; u < 8; u++) {
        int co = cg * 8 + u;
        float v = tf32r(tanhf(fa[u]) * (1.f / (1.f + expf(-ga[u]))));
        mo[(long)co * 1024] = v;
        if (last)
            msk[(long)(layer * 32 + co) * 65536 + b * 1024 + n0 + nl] = v;
    }
}

// ---------------------------------------------------------------------------
// fp32 SIMT SGEMM for ADP^2 = ADP @ ADP (128x128 tile); stores tf32-rounded.
// A = Bm[:,0:1024] (ld 2048), B same, C = Bm + 1024.
// ---------------------------------------------------------------------------
__global__ __launch_bounds__(256) void k_sgemm(const float* __restrict__ A,
                                               const float* __restrict__ B,
                                               float* __restrict__ C,
                                               int K, int lda, int ldb, int ldc) {
    __shared__ float As[16][132];
    __shared__ float Bs[16][128];
    int tid = threadIdx.x;
    int m0 = blockIdx.y * 128, n0 = blockIdx.x * 128;
    int ty = tid >> 4, tx = tid & 15;
    float acc[8][8];
#pragma unroll
    for (int i = 0; i < 8; i++)
#pragma unroll
        for (int j = 0; j < 8; j++) acc[i][j] = 0.f;

    for (int k0 = 0; k0 < K; k0 += 16) {
#pragma unroll
        for (int i = 0; i < 2; i++) {
            int f = tid + i * 256;
            int r = f >> 2, kc = (f & 3) * 4;
            float4 v = *(const float4*)(A + (long)(m0 + r) * lda + k0 + kc);
            As[kc + 0][r] = v.x; As[kc + 1][r] = v.y;
            As[kc + 2][r] = v.z; As[kc + 3][r] = v.w;
        }
#pragma unroll
        for (int i = 0; i < 2; i++) {
            int f = tid + i * 256;
            int r = f >> 5, nc = (f & 31) * 4;
            float4 v = *(const float4*)(B + (long)(k0 + r) * ldb + n0 + nc);
            *(float4*)&Bs[r][nc] = v;
        }
        __syncthreads();
#pragma unroll
        for (int k = 0; k < 16; k++) {
            float a[8], b[8];
            float4 a0 = *(const float4*)&As[k][ty * 8];
            float4 a1 = *(const float4*)&As[k][ty * 8 + 4];
            a[0] = a0.x; a[1] = a0.y; a[2] = a0.z; a[3] = a0.w;
            a[4] = a1.x; a[5] = a1.y; a[6] = a1.z; a[7] = a1.w;
            float4 b0 = *(const float4*)&Bs[k][tx * 8];
            float4 b1 = *(const float4*)&Bs[k][tx * 8 + 4];
            b[0] = b0.x; b[1] = b0.y; b[2] = b0.z; b[3] = b0.w;
            b[4] = b1.x; b[5] = b1.y; b[6] = b1.z; b[7] = b1.w;
#pragma unroll
            for (int i = 0; i < 8; i++)
#pragma unroll
                for (int j = 0; j < 8; j++) acc[i][j] += a[i] * b[j];
        }
        __syncthreads();
    }
#pragma unroll
    for (int i = 0; i < 8; i++) {
        int mrow = m0 + ty * 8 + i;
#pragma unroll
        for (int j = 0; j < 8; j++)
            C[(long)mrow * ldc + n0 + tx * 8 + j] = tf32r(acc[i][j]);
    }
}

// ---------------------------------------------------------------------------
// TF32 tensor-core GEMM, cp.async double-buffered, NO in-loop cvt
// (operands pre-rounded to tf32; raw bits fed to mma).
// CTA tile 128x256, 8 warps, warp tile 64x64 (m16n8k8).
// flags bit1: C = relu(acc + bias[row]). K mult of 32; M mult 128; N mult 256.
// ---------------------------------------------------------------------------
__global__ __launch_bounds__(256) void k_gemm_tf32(const float* __restrict__ A,
                                                   const float* __restrict__ B,
                                                   float* __restrict__ C,
                                                   int K, int lda, long ldb, long ldc,
                                                   const float* __restrict__ bias,
                                                   int flags) {
    __shared__ float As[2][128][36];
    __shared__ float Bs[2][32][260];
    int tid = threadIdx.x;
    int m0 = blockIdx.y * 128;
    long n0 = (long)blockIdx.x * 256;
    int w = tid >> 5, lane = tid & 31;
    int grp = lane >> 2, tg = lane & 3;
    int wm = (w & 1) * 64, wn = (w >> 1) * 64;

    // load coords: A 128x32 (2 thr/row, 16 floats each), B 32x256 (8 thr/row, 32 floats)
    int ar = tid >> 1, ac = (tid & 1) * 16;
    int br = tid >> 3, bc = (tid & 7) * 32;

    float acc[4][8][4];
#pragma unroll
    for (int mt = 0; mt < 4; mt++)
#pragma unroll
        for (int nt = 0; nt < 8; nt++)
#pragma unroll
            for (int c = 0; c < 4; c++) acc[mt][nt][c] = 0.f;

    int nstage = K / 32;
    {
        const float* ag = A + (long)(m0 + ar) * lda + ac;
#pragma unroll
        for (int i = 0; i < 4; i++) cp16(&As[0][ar][ac + i * 4], ag + i * 4);
        const float* bg = B + (long)br * ldb + n0 + bc;
#pragma unroll
        for (int i = 0; i < 8; i++) cp16(&Bs[0][br][bc + i * 4], bg + i * 4);
        asm volatile("cp.async.commit_group;\n");
    }

    for (int s = 0; s < nstage; s++) {
        int buf = s & 1;
        if (s + 1 < nstage) {
            int nb = buf ^ 1;
            int k0 = (s + 1) * 32;
            const float* ag = A + (long)(m0 + ar) * lda + k0 + ac;
#pragma unroll
            for (int i = 0; i < 4; i++) cp16(&As[nb][ar][ac + i * 4], ag + i * 4);
            const float* bg = B + (long)(k0 + br) * ldb + n0 + bc;
#pragma unroll
            for (int i = 0; i < 8; i++) cp16(&Bs[nb][br][bc + i * 4], bg + i * 4);
            asm volatile("cp.async.commit_group;\n");
            asm volatile("cp.async.wait_group 1;\n");
        } else {
            asm volatile("cp.async.wait_group 0;\n");
        }
        __syncthreads();

#pragma unroll
        for (int ks = 0; ks < 4; ks++) {
            int k = ks * 8;
            unsigned a[4][4];
#pragma unroll
            for (int mt = 0; mt < 4; mt++) {
                int rb = wm + mt * 16;
                a[mt][0] = __float_as_uint(As[buf][rb + grp][k + tg]);
                a[mt][1] = __float_as_uint(As[buf][rb + grp + 8][k + tg]);
                a[mt][2] = __float_as_uint(As[buf][rb + grp][k + tg + 4]);
                a[mt][3] = __float_as_uint(As[buf][rb + grp + 8][k + tg + 4]);
            }
            unsigned b[8][2];
#pragma unroll
            for (int nt = 0; nt < 8; nt++) {
                int cb = wn + nt * 8 + grp;
                b[nt][0] = __float_as_uint(Bs[buf][k + tg][cb]);
                b[nt][1] = __float_as_uint(Bs[buf][k + tg + 4][cb]);
            }
#pragma unroll
            for (int mt = 0; mt < 4; mt++)
#pragma unroll
                for (int nt = 0; nt < 8; nt++) {
                    asm volatile(
                        "mma.sync.aligned.m16n8k8.row.col.f32.tf32.tf32.f32 "
                        "{%0,%1,%2,%3}, {%4,%5,%6,%7}, {%8,%9}, {%0,%1,%2,%3};\n"
                        : "+f"(acc[mt][nt][0]), "+f"(acc[mt][nt][1]),
                          "+f"(acc[mt][nt][2]), "+f"(acc[mt][nt][3])
                        : "r"(a[mt][0]), "r"(a[mt][1]), "r"(a[mt][2]), "r"(a[mt][3]),
                          "r"(b[nt][0]), "r"(b[nt][1]));
                }
        }
        __syncthreads();
    }

#pragma unroll
    for (int mt = 0; mt < 4; mt++) {
        int row0 = m0 + wm + mt * 16 + grp;
        int row1 = row0 + 8;
        float b0 = 0.f, b1 = 0.f;
        if (flags & 2) { b0 = bias[row0]; b1 = bias[row1]; }
#pragma unroll
        for (int nt = 0; nt < 8; nt++) {
            long col = n0 + wn + nt * 8 + tg * 2;
            float2 o0, o1;
            if (flags & 2) {
                o0.x = fmaxf(acc[mt][nt][0] + b0, 0.f);
                o0.y = fmaxf(acc[mt][nt][1] + b0, 0.f);
                o1.x = fmaxf(acc[mt][nt][2] + b1, 0.f);
                o1.y = fmaxf(acc[mt][nt][3] + b1, 0.f);
            } else {
                o0.x = acc[mt][nt][0]; o0.y = acc[mt][nt][1];
                o1.x = acc[mt][nt][2]; o1.y = acc[mt][nt][3];
            }
            *(float2*)(C + (long)row0 * ldc + col) = o0;
            *(float2*)(C + (long)row1 * ldc + col) = o1;
        }
    }
}

// ---------------------------------------------------------------------------
// gc mix + residual + BN
// ---------------------------------------------------------------------------
__global__ __launch_bounds__(256) void k_gc(const float* __restrict__ m,
                                            const float* __restrict__ x12,
                                            const float* __restrict__ hold,
                                            const float* __restrict__ gcw,
                                            const float* __restrict__ gcb,
                                            const float* __restrict__ bng,
                                            const float* __restrict__ bnb,
                                            float* __restrict__ hnew,
                                            int L0, int L1, int d) {
    __shared__ float s_in[3][32][64];
    __shared__ float4 s_w[32][32];
    __shared__ float s_b[32], s_sc[32], s_sh[32];
    int bl = blockIdx.x;
    int b = bl / L1, l = bl - b * L1;
    int n0 = blockIdx.y * 64;
    int tid = threadIdx.x;
    for (int idx = tid; idx < 1024; idx += 256) {
        int co = idx >> 5, ci = idx & 31;
        s_w[co][ci] = make_float4(gcw[co * 96 + ci], gcw[co * 96 + 32 + ci],
                                  gcw[co * 96 + 64 + ci], 0.f);
    }
    if (tid < 32) {
        s_b[tid] = gcb[tid];
        s_sc[tid] = bng[tid] * rsqrtf(1.f + 1e-5f);
        s_sh[tid] = bnb[tid];
    }
    const float* mb = m + ((long)(b * L1 + l) * 32) * 1024 + n0;
    const float* xb = x12 + ((long)(b * L1 + l) * 32) * 2048 + n0;
    for (int idx = tid; idx < 2048; idx += 256) {
        int ci = idx >> 6, nl = idx & 63;
        s_in[0][ci][nl] = mb[(long)ci * 1024 + nl];
        s_in[1][ci][nl] = xb[(long)ci * 2048 + nl];
        s_in[2][ci][nl] = xb[(long)ci * 2048 + 1024 + nl];
    }
    __syncthreads();
    int nl = tid & 63, cg = tid >> 6;
    float acc[8];
#pragma unroll
    for (int u = 0; u < 8; u++) acc[u] = s_b[cg * 8 + u];
#pragma unroll
    for (int ci = 0; ci < 32; ci++) {
        float v0 = s_in[0][ci][nl], v1 = s_in[1][ci][nl], v2 = s_in[2][ci][nl];
#pragma unroll
        for (int u = 0; u < 8; u++) {
            float4 w = s_w[cg * 8 + u][ci];
            acc[u] += w.x * v0 + w.y * v1 + w.z * v2;
        }
    }
    const float* rb = hold + ((long)(b * L0 + l + d) * 32) * 1024 + n0 + nl;
    float* ob = hnew + ((long)(b * L1 + l) * 32) * 1024 + n0 + nl;
#pragma unroll
    for (int u = 0; u < 8; u++) {
        int co = cg * 8 + u;
        float res = rb[(long)co * 1024];
        ob[(long)co * 1024] = (acc[u] + res) * s_sc[co] + s_sh[co];
    }
}

// ---------------------------------------------------------------------------
// prep: concat skip weights (tf32-rounded) + summed skip bias; round end1_w
// ---------------------------------------------------------------------------
__global__ __launch_bounds__(256) void k_prep(const float* __restrict__ skw,
                                              const float* __restrict__ skb,
                                              float* __restrict__ wcat,
                                              float* __restrict__ bsum) {
    int co = blockIdx.x, k = threadIdx.x;
    int i = k >> 5, ci = k & 31;
    wcat[co * 256 + k] = tf32r(skw[((long)i * 256 + co) * 32 + ci]);
    if (k == 0) {
        float s = 0.f;
#pragma unroll
        for (int j = 0; j < 8; j++) s += skb[j * 256 + co];
        bsum[co] = s;
    }
}
__global__ __launch_bounds__(256) void k_round(const float* __restrict__ w,
                                               float* __restrict__ o) {
    int i = blockIdx.x * 256 + threadIdx.x;
    o[i] = tf32r(w[i]);
}

// ---------------------------------------------------------------------------
__global__ __launch_bounds__(256) void k_end2(const float* __restrict__ e1,
                                              const float* __restrict__ w2,
                                              const float* __restrict__ b2,
                                              float* __restrict__ out) {
    __shared__ float s_w[12 * 512];
    int tid = threadIdx.x;
    for (int idx = tid; idx < 6144; idx += 256) s_w[idx] = w2[idx];
    __syncthreads();
    int col = blockIdx.x * 256 + tid;
    int b = col >> 10, n = col & 1023;
    float acc[12];
#pragma unroll
    for (int o = 0; o < 12; o++) acc[o] = b2[o];
    for (int c = 0; c < 512; c++) {
        float v = e1[(long)c * 65536 + col];
#pragma unroll
        for (int o = 0; o < 12; o++) acc[o] += s_w[o * 512 + c] * v;
    }
#pragma unroll
    for (int o = 0; o < 12; o++) out[((long)b * 12 + o) * 1024 + n] = acc[o];
}

// ---------------------------------------------------------------------------
extern "C" void kernel_launch(void* const* d_in, const int* in_sizes, int n_in,
                              void* d_out, int out_size) {
    const float* x        = (const float*)d_in[0];
    const float* start_w  = (const float*)d_in[1];
    const float* start_b  = (const float*)d_in[2];
    const float* nodevec1 = (const float*)d_in[3];
    const float* nodevec2 = (const float*)d_in[4];
    const float* filter_w = (const float*)d_in[5];
    const float* filter_b = (const float*)d_in[6];
    const float* gate_w   = (const float*)d_in[7];
    const float* gate_b   = (const float*)d_in[8];
    const float* skip_w   = (const float*)d_in[9];
    const float* skip_b   = (const float*)d_in[10];
    const float* gc_w     = (const float*)d_in[11];
    const float* gc_b     = (const float*)d_in[12];
    const float* bn_g     = (const float*)d_in[13];
    const float* bn_b     = (const float*)d_in[14];
    const float* end1_w   = (const float*)d_in[15];
    const float* end1_b   = (const float*)d_in[16];
    const float* end2_w   = (const float*)d_in[17];
    const float* end2_b   = (const float*)d_in[18];

    float *hA, *hB, *m, *x12, *Bm, *msk, *skip, *e1, *w1r, *wsk, *bsk;
    cudaGetSymbolAddress((void**)&hA, g_hA);
    cudaGetSymbolAddress((void**)&hB, g_hB);
    cudaGetSymbolAddress((void**)&m, g_m);
    cudaGetSymbolAddress((void**)&x12, g_x12);
    cudaGetSymbolAddress((void**)&Bm, g_Bm);
    cudaGetSymbolAddress((void**)&msk, g_msk);
    cudaGetSymbolAddress((void**)&skip, g_skip);
    cudaGetSymbolAddress((void**)&e1, g_e1);
    cudaGetSymbolAddress((void**)&w1r, g_w1r);
    cudaGetSymbolAddress((void**)&wsk, g_wsk);
    cudaGetSymbolAddress((void**)&bsk, g_bsk);

    // adjacency (tf32-rounded) + ADP^2 (fp32 accumulate, rounded store)
    k_adp<<<1024, 256>>>(nodevec1, nodevec2, Bm);
    k_sgemm<<<dim3(8, 8), 256>>>(Bm, Bm, Bm + 1024, 1024, 2048, 2048, 2048);
    k_start<<<dim3(64 * 13, 4), 256>>>(x, start_w, start_b, hA);
    k_round<<<512, 256>>>(end1_w, w1r);
    k_prep<<<256, 256>>>(skip_w, skip_b, wsk, bsk);

    const int lens[9] = {13, 12, 10, 9, 7, 6, 4, 3, 1};
    const int dil[8]  = {1, 2, 1, 2, 1, 2, 1, 2};
    float* hcur = hA;
    float* hnext = hB;

    for (int i = 0; i < 8; i++) {
        int L0 = lens[i], L1 = lens[i + 1], d = dil[i];
        k_dconv<<<dim3(64 * L1, 16), 256>>>(hcur,
                                            filter_w + i * 2048, filter_b + i * 32,
                                            gate_w + i * 2048, gate_b + i * 32,
                                            m, msk, L0, L1, d, i);
        if (i < 7) {
            int M = 2048 * L1;
            // x12 = m @ [ADP | ADP^2]
            k_gemm_tf32<<<dim3(2048 / 256, M / 128), 256>>>(
                m, Bm, x12, 1024, 1024, 2048, 2048, nullptr, 0);
            k_gc<<<dim3(64 * L1, 16), 256>>>(m, x12, hcur,
                                             gc_w + i * 32 * 96, gc_b + i * 32,
                                             bn_g + i * 32, bn_b + i * 32,
                                             hnext, L0, L1, d);
            float* t = hcur; hcur = hnext; hnext = t;
        }
    }

    // skip = relu(Wcat @ msk + bsum)   (replaces 8 accumulation launches)
    k_gemm_tf32<<<dim3(65536 / 256, 2), 256>>>(
        wsk, msk, skip, 256, 256, 65536, 65536, bsk, 2);
    // e1 = relu(W1 @ skip + b1)
    k_gemm_tf32<<<dim3(65536 / 256, 4), 256>>>(
        w1r, skip, e1, 256, 256, 65536, 65536, end1_b, 2);
    k_end2<<<256, 256>>>(e1, end2_w, end2_b, (float*)d_out);
}

// round 8
// speedup vs baseline: 3.7180x; 1.6453x over previous
#include <cuda_runtime.h>
#include <cuda_fp16.h>
#include <math.h>
#include <stdint.h>

// ---------------------------------------------------------------------------
// GWNet2: B=64, N=1024, L=13, RC=DC=32, SC=256, EC=512, OUT=12, LAYERS=8
// h layout: [B][L][C][N] fp32. m: same layout, fp16. x12/e1: fp32.
// GEMMs: mma.sync m16n8k16 f16 inputs, f32 accumulate. B operands k-packed
// as half2(B[2i][n], B[2i+1][n]) so fragments load with one LDS.32.
// ---------------------------------------------------------------------------

__device__ float  g_hA  [64 * 13 * 32 * 1024];
__device__ float  g_hB  [64 * 12 * 32 * 1024];
__device__ __half g_m   [64 * 12 * 32 * 1024];       // fp16 A operand
__device__ float  g_x12 [64 * 12 * 32 * 2048];       // (x1 | x2) fp32
__device__ float  g_adpf[1024 * 1024];               // ADP fp32 (for ADP^2)
__device__ __half g_Bm  [2048 * 2048];               // k-packed [ADP | ADP^2]
__device__ __half g_msk [256 * 65536];               // k-packed concat m_last
__device__ __half g_skip[256 * 65536];               // k-packed relu(skip)
__device__ float  g_e1  [512 * 65536];               // fp32
__device__ __half g_w1r [512 * 256];
__device__ __half g_wsk [256 * 256];
__device__ float  g_bsk [256];

// ---------------------------------------------------------------------------
__device__ __forceinline__ void cp16(void* smem, const void* g) {
    unsigned s = (unsigned)__cvta_generic_to_shared(smem);
    asm volatile("cp.async.cg.shared.global [%0], [%1], 16;\n" :: "r"(s), "l"(g));
}

// ---------------------------------------------------------------------------
// adp = softmax(relu(nv1 @ nv2), axis=1) -> fp32 g_adpf + k-packed half g_Bm
// (columns 0..1023 of the fused B matrix)
// ---------------------------------------------------------------------------
__global__ __launch_bounds__(256) void k_adp(const float* __restrict__ nv1,
                                             const float* __restrict__ nv2,
                                             float* __restrict__ adpf,
                                             __half* __restrict__ Bpk) {
    __shared__ float red[256];
    int v = blockIdx.x, tid = threadIdx.x;
    float n1[10];
#pragma unroll
    for (int k = 0; k < 10; k++) n1[k] = nv1[v * 10 + k];
    float a[4];
#pragma unroll
    for (int j = 0; j < 4; j++) {
        int w = tid + j * 256;
        float s = 0.f;
#pragma unroll
        for (int k = 0; k < 10; k++) s += n1[k] * nv2[k * 1024 + w];
        a[j] = fmaxf(s, 0.f);
    }
    float mx = fmaxf(fmaxf(a[0], a[1]), fmaxf(a[2], a[3]));
    red[tid] = mx; __syncthreads();
    for (int s = 128; s > 0; s >>= 1) {
        if (tid < s) red[tid] = fmaxf(red[tid], red[tid + s]);
        __syncthreads();
    }
    mx = red[0]; __syncthreads();
    float e[4]; float sum = 0.f;
#pragma unroll
    for (int j = 0; j < 4; j++) { e[j] = expf(a[j] - mx); sum += e[j]; }
    red[tid] = sum; __syncthreads();
    for (int s = 128; s > 0; s >>= 1) {
        if (tid < s) red[tid] += red[tid + s];
        __syncthreads();
    }
    float inv = 1.f / red[0];
#pragma unroll
    for (int j = 0; j < 4; j++) {
        int w = tid + j * 256;
        float val = e[j] * inv;
        adpf[(long)v * 1024 + w] = val;
        Bpk[((long)(v >> 1) * 2048 + w) * 2 + (v & 1)] = __float2half(val);
    }
}

// ---------------------------------------------------------------------------
__global__ __launch_bounds__(256) void k_start(const float* __restrict__ x,
                                               const float* __restrict__ sw,
                                               const float* __restrict__ sb,
                                               float* __restrict__ h) {
    int bl = blockIdx.x;
    int b = bl / 13, l = bl - b * 13;
    int n = blockIdx.y * 256 + threadIdx.x;
    float x0 = x[(((long)b * 2 + 0) * 1024 + n) * 13 + l];
    float x1 = x[(((long)b * 2 + 1) * 1024 + n) * 13 + l];
    float* hb = h + ((long)(b * 13 + l) * 32) * 1024 + n;
#pragma unroll
    for (int c = 0; c < 32; c++)
        hb[(long)c * 1024] = sw[c * 2] * x0 + sw[c * 2 + 1] * x1 + sb[c];
}

// ---------------------------------------------------------------------------
// dilated conv + tanh*sigmoid; m out fp16; last timestep also k-packed to msk
// ---------------------------------------------------------------------------
__global__ __launch_bounds__(256) void k_dconv(const float* __restrict__ h,
                                               const float* __restrict__ fw,
                                               const float* __restrict__ fb,
                                               const float* __restrict__ gw,
                                               const float* __restrict__ gb,
                                               __half* __restrict__ m,
                                               __half* __restrict__ msk,
                                               int L0, int L1, int d, int layer) {
    __shared__ float s_in[2][32][64];
    __shared__ float4 s_w[32][32];
    __shared__ float s_fb[32], s_gb[32];
    int bl = blockIdx.x;
    int b = bl / L1, l = bl - b * L1;
    int n0 = blockIdx.y * 64;
    int tid = threadIdx.x;
    for (int idx = tid; idx < 1024; idx += 256) {
        int co = idx >> 5, ci = idx & 31;
        int o = (co * 32 + ci) * 2;
        s_w[co][ci] = make_float4(fw[o], fw[o + 1], gw[o], gw[o + 1]);
    }
    if (tid < 32) { s_fb[tid] = fb[tid]; s_gb[tid] = gb[tid]; }
    const float* hb = h + ((long)(b * L0 + l) * 32) * 1024 + n0;
    for (int idx = tid; idx < 4096; idx += 256) {
        int tap = idx >> 11, ci = (idx >> 6) & 31, nl = idx & 63;
        s_in[tap][ci][nl] = hb[((long)(tap * d) * 32 + ci) * 1024 + nl];
    }
    __syncthreads();
    int nl = tid & 63, cg = tid >> 6;
    float fa[8], ga[8];
#pragma unroll
    for (int u = 0; u < 8; u++) { fa[u] = s_fb[cg * 8 + u]; ga[u] = s_gb[cg * 8 + u]; }
#pragma unroll
    for (int ci = 0; ci < 32; ci++) {
        float v0 = s_in[0][ci][nl], v1 = s_in[1][ci][nl];
#pragma unroll
        for (int u = 0; u < 8; u++) {
            float4 w = s_w[cg * 8 + u][ci];
            fa[u] += w.x * v0 + w.y * v1;
            ga[u] += w.z * v0 + w.w * v1;
        }
    }
    __half* mo = m + ((long)(b * L1 + l) * 32) * 1024 + n0 + nl;
    bool last = (l == L1 - 1);
    long col = (long)b * 1024 + n0 + nl;
#pragma unroll
    for (int u = 0; u < 8; u++) {
        int co = cg * 8 + u;
        __half v = __float2half(tanhf(fa[u]) * (1.f / (1.f + expf(-ga[u]))));
        mo[(long)co * 1024] = v;
        if (last) {
            int k = layer * 32 + co;
            msk[((long)(k >> 1) * 65536 + col) * 2 + (k & 1)] = v;
        }
    }
}

// ---------------------------------------------------------------------------
// fp32 SIMT SGEMM: ADP^2 = ADP @ ADP; stores k-packed half into Bpk at
// COLUMNS 1024..2047 (same k rows as ADP — fused [ADP | ADP^2] B matrix).
// ---------------------------------------------------------------------------
__global__ __launch_bounds__(256) void k_sgemm(const float* __restrict__ A,
                                               const float* __restrict__ B,
                                               __half* __restrict__ Bpk) {
    __shared__ float As[16][132];
    __shared__ float Bs[16][128];
    int tid = threadIdx.x;
    int m0 = blockIdx.y * 128, n0 = blockIdx.x * 128;
    int ty = tid >> 4, tx = tid & 15;
    float acc[8][8];
#pragma unroll
    for (int i = 0; i < 8; i++)
#pragma unroll
        for (int j = 0; j < 8; j++) acc[i][j] = 0.f;

    for (int k0 = 0; k0 < 1024; k0 += 16) {
#pragma unroll
        for (int i = 0; i < 2; i++) {
            int f = tid + i * 256;
            int r = f >> 2, kc = (f & 3) * 4;
            float4 v = *(const float4*)(A + (long)(m0 + r) * 1024 + k0 + kc);
            As[kc + 0][r] = v.x; As[kc + 1][r] = v.y;
            As[kc + 2][r] = v.z; As[kc + 3][r] = v.w;
        }
#pragma unroll
        for (int i = 0; i < 2; i++) {
            int f = tid + i * 256;
            int r = f >> 5, nc = (f & 31) * 4;
            float4 v = *(const float4*)(B + (long)(k0 + r) * 1024 + n0 + nc);
            *(float4*)&Bs[r][nc] = v;
        }
        __syncthreads();
#pragma unroll
        for (int k = 0; k < 16; k++) {
            float a[8], b[8];
            float4 a0 = *(const float4*)&As[k][ty * 8];
            float4 a1 = *(const float4*)&As[k][ty * 8 + 4];
            a[0] = a0.x; a[1] = a0.y; a[2] = a0.z; a[3] = a0.w;
            a[4] = a1.x; a[5] = a1.y; a[6] = a1.z; a[7] = a1.w;
            float4 b0 = *(const float4*)&Bs[k][tx * 8];
            float4 b1 = *(const float4*)&Bs[k][tx * 8 + 4];
            b[0] = b0.x; b[1] = b0.y; b[2] = b0.z; b[3] = b0.w;
            b[4] = b1.x; b[5] = b1.y; b[6] = b1.z; b[7] = b1.w;
#pragma unroll
            for (int i = 0; i < 8; i++)
#pragma unroll
                for (int j = 0; j < 8; j++) acc[i][j] += a[i] * b[j];
        }
        __syncthreads();
    }
#pragma unroll
    for (int i = 0; i < 8; i++) {
        int v = m0 + ty * 8 + i;   // k row index
#pragma unroll
        for (int j = 0; j < 8; j++) {
            int w = n0 + tx * 8 + j;
            Bpk[((long)(v >> 1) * 2048 + 1024 + w) * 2 + (v & 1)] =
                __float2half(acc[i][j]);
        }
    }
}

// ---------------------------------------------------------------------------
// fp16 tensor-core GEMM (m16n8k16, f32 acc), cp.async double-buffered.
// C[M,N] = A[M,K] @ B[K,N]. A: half, row-major (lda halves). B: k-packed half2
// (ldb2 = N stride in half2). CTA 128x256, 8 warps, warp tile 64x64.
// flags bit1: +bias[row], relu. bit2: C stored k-packed half (else fp32).
// M mult 128, N mult 256, K mult 32.
// ---------------------------------------------------------------------------
__global__ __launch_bounds__(256) void k_gemm_f16(const __half* __restrict__ A,
                                                  const half2* __restrict__ Bpk,
                                                  void* __restrict__ Cv,
                                                  int K, int lda, long ldb2, long ldc,
                                                  const float* __restrict__ bias,
                                                  int flags) {
    __shared__ __half As[2][128][40];    // [m][k halves], pad 40 (20 words)
    __shared__ half2  Bs[2][16][264];    // [k/2][n], pad 264
    int tid = threadIdx.x;
    int m0 = blockIdx.y * 128;
    long n0 = (long)blockIdx.x * 256;
    int w = tid >> 5, lane = tid & 31;
    int grp = lane >> 2, tg = lane & 3;
    int wm = (w & 1) * 64, wn = (w >> 1) * 64;

    float acc[4][8][4];
#pragma unroll
    for (int mt = 0; mt < 4; mt++)
#pragma unroll
        for (int nt = 0; nt < 8; nt++)
#pragma unroll
            for (int c = 0; c < 4; c++) acc[mt][nt][c] = 0.f;

    int nstage = K / 32;
    {
#pragma unroll
        for (int i = 0; i < 2; i++) {
            int ch = tid + i * 256;
            int r = ch >> 2, p = (ch & 3) * 8;
            cp16(&As[0][r][p], A + (long)(m0 + r) * lda + p);
        }
#pragma unroll
        for (int i = 0; i < 4; i++) {
            int ch = tid + i * 256;
            int r = ch >> 6, c4 = (ch & 63) * 4;
            cp16(&Bs[0][r][c4], Bpk + (long)r * ldb2 + n0 + c4);
        }
        asm volatile("cp.async.commit_group;\n");
    }

    for (int s = 0; s < nstage; s++) {
        int buf = s & 1;
        if (s + 1 < nstage) {
            int nb = buf ^ 1;
            int k0 = (s + 1) * 32;
#pragma unroll
            for (int i = 0; i < 2; i++) {
                int ch = tid + i * 256;
                int r = ch >> 2, p = (ch & 3) * 8;
                cp16(&As[nb][r][p], A + (long)(m0 + r) * lda + k0 + p);
            }
#pragma unroll
            for (int i = 0; i < 4; i++) {
                int ch = tid + i * 256;
                int r = ch >> 6, c4 = (ch & 63) * 4;
                cp16(&Bs[nb][r][c4], Bpk + (long)(k0 / 2 + r) * ldb2 + n0 + c4);
            }
            asm volatile("cp.async.commit_group;\n");
            asm volatile("cp.async.wait_group 1;\n");
        } else {
            asm volatile("cp.async.wait_group 0;\n");
        }
        __syncthreads();

#pragma unroll
        for (int s2 = 0; s2 < 2; s2++) {
            unsigned a[4][4];
#pragma unroll
            for (int mt = 0; mt < 4; mt++) {
                int rb = wm + mt * 16;
                a[mt][0] = *(const unsigned*)&As[buf][rb + grp][s2 * 16 + tg * 2];
                a[mt][1] = *(const unsigned*)&As[buf][rb + grp + 8][s2 * 16 + tg * 2];
                a[mt][2] = *(const unsigned*)&As[buf][rb + grp][s2 * 16 + tg * 2 + 8];
                a[mt][3] = *(const unsigned*)&As[buf][rb + grp + 8][s2 * 16 + tg * 2 + 8];
            }
            unsigned b[8][2];
#pragma unroll
            for (int nt = 0; nt < 8; nt++) {
                int cb = wn + nt * 8 + grp;
                b[nt][0] = *(const unsigned*)&Bs[buf][s2 * 8 + tg][cb];
                b[nt][1] = *(const unsigned*)&Bs[buf][s2 * 8 + tg + 4][cb];
            }
#pragma unroll
            for (int mt = 0; mt < 4; mt++)
#pragma unroll
                for (int nt = 0; nt < 8; nt++) {
                    asm volatile(
                        "mma.sync.aligned.m16n8k16.row.col.f32.f16.f16.f32 "
                        "{%0,%1,%2,%3}, {%4,%5,%6,%7}, {%8,%9}, {%0,%1,%2,%3};\n"
                        : "+f"(acc[mt][nt][0]), "+f"(acc[mt][nt][1]),
                          "+f"(acc[mt][nt][2]), "+f"(acc[mt][nt][3])
                        : "r"(a[mt][0]), "r"(a[mt][1]), "r"(a[mt][2]), "r"(a[mt][3]),
                          "r"(b[nt][0]), "r"(b[nt][1]));
                }
        }
        __syncthreads();
    }

    float* Cf = (float*)Cv;
    __half* Ch = (__half*)Cv;
#pragma unroll
    for (int mt = 0; mt < 4; mt++) {
        int row0 = m0 + wm + mt * 16 + grp;
        int row1 = row0 + 8;
        float b0 = 0.f, b1 = 0.f;
        if (flags & 2) { b0 = bias[row0]; b1 = bias[row1]; }
#pragma unroll
        for (int nt = 0; nt < 8; nt++) {
            long col = n0 + wn + nt * 8 + tg * 2;
            float v00 = acc[mt][nt][0], v01 = acc[mt][nt][1];
            float v10 = acc[mt][nt][2], v11 = acc[mt][nt][3];
            if (flags & 2) {
                v00 = fmaxf(v00 + b0, 0.f); v01 = fmaxf(v01 + b0, 0.f);
                v10 = fmaxf(v10 + b1, 0.f); v11 = fmaxf(v11 + b1, 0.f);
            }
            if (flags & 4) {
                long p0 = ((long)(row0 >> 1) * ldc + col) * 2 + (row0 & 1);
                long p1 = ((long)(row1 >> 1) * ldc + col) * 2 + (row1 & 1);
                Ch[p0] = __float2half(v00); Ch[p0 + 2] = __float2half(v01);
                Ch[p1] = __float2half(v10); Ch[p1 + 2] = __float2half(v11);
            } else {
                *(float2*)(Cf + (long)row0 * ldc + col) = make_float2(v00, v01);
                *(float2*)(Cf + (long)row1 * ldc + col) = make_float2(v10, v11);
            }
        }
    }
}

// ---------------------------------------------------------------------------
// gc mix + residual + BN (m read as fp16)
// ---------------------------------------------------------------------------
__global__ __launch_bounds__(256) void k_gc(const __half* __restrict__ m,
                                            const float* __restrict__ x12,
                                            const float* __restrict__ hold,
                                            const float* __restrict__ gcw,
                                            const float* __restrict__ gcb,
                                            const float* __restrict__ bng,
                                            const float* __restrict__ bnb,
                                            float* __restrict__ hnew,
                                            int L0, int L1, int d) {
    __shared__ float s_in[3][32][64];
    __shared__ float4 s_w[32][32];
    __shared__ float s_b[32], s_sc[32], s_sh[32];
    int bl = blockIdx.x;
    int b = bl / L1, l = bl - b * L1;
    int n0 = blockIdx.y * 64;
    int tid = threadIdx.x;
    for (int idx = tid; idx < 1024; idx += 256) {
        int co = idx >> 5, ci = idx & 31;
        s_w[co][ci] = make_float4(gcw[co * 96 + ci], gcw[co * 96 + 32 + ci],
                                  gcw[co * 96 + 64 + ci], 0.f);
    }
    if (tid < 32) {
        s_b[tid] = gcb[tid];
        s_sc[tid] = bng[tid] * rsqrtf(1.f + 1e-5f);
        s_sh[tid] = bnb[tid];
    }
    const __half* mb = m + ((long)(b * L1 + l) * 32) * 1024 + n0;
    const float* xb = x12 + ((long)(b * L1 + l) * 32) * 2048 + n0;
    for (int idx = tid; idx < 2048; idx += 256) {
        int ci = idx >> 6, nl = idx & 63;
        s_in[0][ci][nl] = __half2float(mb[(long)ci * 1024 + nl]);
        s_in[1][ci][nl] = xb[(long)ci * 2048 + nl];
        s_in[2][ci][nl] = xb[(long)ci * 2048 + 1024 + nl];
    }
    __syncthreads();
    int nl = tid & 63, cg = tid >> 6;
    float acc[8];
#pragma unroll
    for (int u = 0; u < 8; u++) acc[u] = s_b[cg * 8 + u];
#pragma unroll
    for (int ci = 0; ci < 32; ci++) {
        float v0 = s_in[0][ci][nl], v1 = s_in[1][ci][nl], v2 = s_in[2][ci][nl];
#pragma unroll
        for (int u = 0; u < 8; u++) {
            float4 w = s_w[cg * 8 + u][ci];
            acc[u] += w.x * v0 + w.y * v1 + w.z * v2;
        }
    }
    const float* rb = hold + ((long)(b * L0 + l + d) * 32) * 1024 + n0 + nl;
    float* ob = hnew + ((long)(b * L1 + l) * 32) * 1024 + n0 + nl;
#pragma unroll
    for (int u = 0; u < 8; u++) {
        int co = cg * 8 + u;
        float res = rb[(long)co * 1024];
        ob[(long)co * 1024] = (acc[u] + res) * s_sc[co] + s_sh[co];
    }
}

// ---------------------------------------------------------------------------
// prep: concat skip weights (half) + summed skip bias; round end1_w to half
// ---------------------------------------------------------------------------
__global__ __launch_bounds__(256) void k_prep(const float* __restrict__ skw,
                                              const float* __restrict__ skb,
                                              __half* __restrict__ wcat,
                                              float* __restrict__ bsum) {
    int co = blockIdx.x, k = threadIdx.x;
    int i = k >> 5, ci = k & 31;
    wcat[co * 256 + k] = __float2half(skw[((long)i * 256 + co) * 32 + ci]);
    if (k == 0) {
        float s = 0.f;
#pragma unroll
        for (int j = 0; j < 8; j++) s += skb[j * 256 + co];
        bsum[co] = s;
    }
}
__global__ __launch_bounds__(256) void k_roundh(const float* __restrict__ w,
                                                __half* __restrict__ o) {
    int i = blockIdx.x * 256 + threadIdx.x;
    o[i] = __float2half(w[i]);
}

// ---------------------------------------------------------------------------
__global__ __launch_bounds__(256) void k_end2(const float* __restrict__ e1,
                                              const float* __restrict__ w2,
                                              const float* __restrict__ b2,
                                              float* __restrict__ out) {
    __shared__ float s_w[12 * 512];
    int tid = threadIdx.x;
    for (int idx = tid; idx < 6144; idx += 256) s_w[idx] = w2[idx];
    __syncthreads();
    int col = blockIdx.x * 256 + tid;
    int b = col >> 10, n = col & 1023;
    float acc[12];
#pragma unroll
    for (int o = 0; o < 12; o++) acc[o] = b2[o];
    for (int c = 0; c < 512; c++) {
        float v = e1[(long)c * 65536 + col];
#pragma unroll
        for (int o = 0; o < 12; o++) acc[o] += s_w[o * 512 + c] * v;
    }
#pragma unroll
    for (int o = 0; o < 12; o++) out[((long)b * 12 + o) * 1024 + n] = acc[o];
}

// ---------------------------------------------------------------------------
extern "C" void kernel_launch(void* const* d_in, const int* in_sizes, int n_in,
                              void* d_out, int out_size) {
    const float* x        = (const float*)d_in[0];
    const float* start_w  = (const float*)d_in[1];
    const float* start_b  = (const float*)d_in[2];
    const float* nodevec1 = (const float*)d_in[3];
    const float* nodevec2 = (const float*)d_in[4];
    const float* filter_w = (const float*)d_in[5];
    const float* filter_b = (const float*)d_in[6];
    const float* gate_w   = (const float*)d_in[7];
    const float* gate_b   = (const float*)d_in[8];
    const float* skip_w   = (const float*)d_in[9];
    const float* skip_b   = (const float*)d_in[10];
    const float* gc_w     = (const float*)d_in[11];
    const float* gc_b     = (const float*)d_in[12];
    const float* bn_g     = (const float*)d_in[13];
    const float* bn_b     = (const float*)d_in[14];
    const float* end1_w   = (const float*)d_in[15];
    const float* end1_b   = (const float*)d_in[16];
    const float* end2_w   = (const float*)d_in[17];
    const float* end2_b   = (const float*)d_in[18];

    float *hA, *hB, *x12, *adpf, *e1, *bsk;
    __half *m, *Bm, *msk, *skip, *w1r, *wsk;
    cudaGetSymbolAddress((void**)&hA, g_hA);
    cudaGetSymbolAddress((void**)&hB, g_hB);
    cudaGetSymbolAddress((void**)&m, g_m);
    cudaGetSymbolAddress((void**)&x12, g_x12);
    cudaGetSymbolAddress((void**)&adpf, g_adpf);
    cudaGetSymbolAddress((void**)&Bm, g_Bm);
    cudaGetSymbolAddress((void**)&msk, g_msk);
    cudaGetSymbolAddress((void**)&skip, g_skip);
    cudaGetSymbolAddress((void**)&e1, g_e1);
    cudaGetSymbolAddress((void**)&w1r, g_w1r);
    cudaGetSymbolAddress((void**)&wsk, g_wsk);
    cudaGetSymbolAddress((void**)&bsk, g_bsk);

    k_adp<<<1024, 256>>>(nodevec1, nodevec2, adpf, Bm);
    k_sgemm<<<dim3(8, 8), 256>>>(adpf, adpf, Bm);
    k_start<<<dim3(64 * 13, 4), 256>>>(x, start_w, start_b, hA);
    k_roundh<<<512, 256>>>(end1_w, w1r);
    k_prep<<<256, 256>>>(skip_w, skip_b, wsk, bsk);

    const int lens[9] = {13, 12, 10, 9, 7, 6, 4, 3, 1};
    const int dil[8]  = {1, 2, 1, 2, 1, 2, 1, 2};
    float* hcur = hA;
    float* hnext = hB;

    for (int i = 0; i < 8; i++) {
        int L0 = lens[i], L1 = lens[i + 1], d = dil[i];
        k_dconv<<<dim3(64 * L1, 16), 256>>>(hcur,
                                            filter_w + i * 2048, filter_b + i * 32,
                                            gate_w + i * 2048, gate_b + i * 32,
                                            m, msk, L0, L1, d, i);
        if (i < 7) {
            int M = 2048 * L1;
            // x12 = m @ [ADP | ADP^2]
            k_gemm_f16<<<dim3(2048 / 256, M / 128), 256>>>(
                m, (const half2*)Bm, x12, 1024, 1024, 2048, 2048, nullptr, 0);
            k_gc<<<dim3(64 * L1, 16), 256>>>(m, x12, hcur,
                                             gc_w + i * 32 * 96, gc_b + i * 32,
                                             bn_g + i * 32, bn_b + i * 32,
                                             hnext, L0, L1, d);
            float* t = hcur; hcur = hnext; hnext = t;
        }
    }

    // skip = relu(Wcat @ msk + bsum), stored k-packed half
    k_gemm_f16<<<dim3(65536 / 256, 2), 256>>>(
        wsk, (const half2*)msk, skip, 256, 256, 65536, 65536, bsk, 2 | 4);
    // e1 = relu(W1 @ skip + b1), fp32
    k_gemm_f16<<<dim3(65536 / 256, 4), 256>>>(
        w1r, (const half2*)skip, e1, 256, 256, 65536, 65536, end1_b, 2);
    k_end2<<<256, 256>>>(e1, end2_w, end2_b, (float*)d_out);
}